// round 8
// baseline (speedup 1.0000x reference)
#include <cuda_runtime.h>
#include <cuda_fp16.h>
#include <math.h>
#include <stdint.h>

typedef unsigned long long u64;
typedef __half h16;

#define BB 2
#define SS 1024
#define HID 3072
#define NH 16
#define QL 1536
#define KVL 512
#define NOPEd 128
#define ROPEd 64
#define QKD 192
#define VHD 128
#define NT (BB*SS)
#define KVOUT 256
#define KVA_N 576          /* KVL + ROPE */
#define KVA_NP 640         /* padded to multiple of 128 */
#define SCALE 0.07216878364870323f

// ------------------------------------------------------------------
// scratch (device globals)
// ------------------------------------------------------------------
#define AL __align__(256)
__device__ AL h16   g_hs_h [NT*HID],      g_hs_l [NT*HID];
__device__ AL h16   g_wqa [QL*HID];
__device__ AL h16   g_wqb [HID*QL];
__device__ AL h16   g_wkva[KVA_NP*HID];
__device__ AL h16   g_wkvb[NH*KVOUT*KVL];
__device__ AL h16   g_wo  [HID*NH*VHD];
__device__ AL float g_qlat[NT*QL];
__device__ AL h16   g_qln_h[NT*QL],       g_qln_l[NT*QL];
__device__ AL float g_q   [NT*HID];
__device__ AL float g_kv  [NT*KVA_N];
__device__ AL h16   g_kvln_h[NT*KVL],     g_kvln_l[NT*KVL];
__device__ AL float g_kvb [NT*NH*KVOUT];
__device__ AL h16   g_Qh_h[(u64)BB*NH*SS*QKD], g_Qh_l[(u64)BB*NH*SS*QKD];
__device__ AL h16   g_Kh  [(u64)BB*NH*SS*QKD];
__device__ AL h16   g_Vt  [(u64)BB*NH*VHD*SS];   /* [b][h][d][t] */
__device__ AL float g_sc  [(u64)BB*NH*SS*SS];
__device__ AL h16   g_P_h [(u64)BB*NH*SS*SS],  g_P_l [(u64)BB*NH*SS*SS];
__device__ AL h16   g_at_h[NT*NH*VHD],    g_at_l[NT*NH*VHD];

// ------------------------------------------------------------------
// PTX helpers (sm_80+ ISA: cp.async / ldmatrix / mma.sync fp16)
// ------------------------------------------------------------------
__device__ __forceinline__ uint32_t smem_u32(const void* p) {
    uint32_t a;
    asm("{ .reg .u64 t; cvta.to.shared.u64 t, %1; cvt.u32.u64 %0, t; }" : "=r"(a) : "l"(p));
    return a;
}
__device__ __forceinline__ void cp16(uint32_t dst, const void* src) {
    asm volatile("cp.async.cg.shared.global [%0], [%1], 16;" :: "r"(dst), "l"(src));
}
__device__ __forceinline__ void cp_commit() {
    asm volatile("cp.async.commit_group;" ::: "memory");
}
template<int N> __device__ __forceinline__ void cp_wait() {
    asm volatile("cp.async.wait_group %0;" :: "n"(N) : "memory");
}
__device__ __forceinline__ void ldm4(uint32_t* r, uint32_t addr) {
    asm volatile("ldmatrix.sync.aligned.m8n8.x4.shared.b16 {%0,%1,%2,%3}, [%4];"
        : "=r"(r[0]), "=r"(r[1]), "=r"(r[2]), "=r"(r[3]) : "r"(addr));
}
__device__ __forceinline__ void mma_f16(float* c, const uint32_t* a, uint32_t b0, uint32_t b1) {
    asm volatile(
        "mma.sync.aligned.m16n8k16.row.col.f32.f16.f16.f32 "
        "{%0,%1,%2,%3}, {%4,%5,%6,%7}, {%8,%9}, {%0,%1,%2,%3};"
        : "+f"(c[0]), "+f"(c[1]), "+f"(c[2]), "+f"(c[3])
        : "r"(a[0]), "r"(a[1]), "r"(a[2]), "r"(a[3]), "r"(b0), "r"(b1));
}

// ------------------------------------------------------------------
// fp16 2-term split GEMM: C[m][n] = sum_k (Ah+Al)[m][k]*B[n][k]
// tile 128x128, BK=32, 256 threads (2x4 warps, 64x32 warp tile),
// 4-stage cp.async pipeline, padded smem stride 40 h16 (80 B).
// mode 0: C = acc + bias (float out, ldc=Nw, store-guard n<Nw)
// mode 1: scores: acc*SCALE + mask  (z = bh)
// mode 2: PV: split to Oh/Ol with head scatter (z = bh)
// ------------------------------------------------------------------
#define LDSX 40
#define TSZ  (128*LDSX)          /* elems per tile (5120) */
#define STGB (3*TSZ*2)           /* bytes per stage (30720): Ah, Al, B */
#define NSTG 4
#define SMEM_BYTES (NSTG*STGB)   /* 122880 bytes */

__global__ void __launch_bounds__(256, 1)
k_mma(const h16* __restrict__ Ah, const h16* __restrict__ Al,
      const h16* __restrict__ B,
      float* __restrict__ C, const float* __restrict__ bias,
      const float* __restrict__ mask,
      h16* __restrict__ Oh, h16* __restrict__ Ol,
      int M, int N, int K, int Nw, int mode)
{
    extern __shared__ h16 sm[];
    const uint32_t sb = smem_u32(sm);

    const int tid  = threadIdx.x;
    const int wid  = tid >> 5, lane = tid & 31;
    const int wm   = (wid & 1) * 64;      // warp M offset in tile
    const int wn   = (wid >> 1) * 32;     // warp N offset in tile
    const int z    = blockIdx.z;
    const int m0   = blockIdx.y * 128, n0 = blockIdx.x * 128;

    if (mode == 1) {
        Ah += (u64)z*SS*QKD; Al += (u64)z*SS*QKD;
        B  += (u64)z*SS*QKD;
        C  += (u64)z*SS*SS;
    } else if (mode == 2) {
        Ah += (u64)z*SS*SS;  Al += (u64)z*SS*SS;
        B  += (u64)z*VHD*SS;
    }

    const u64 aoff0 = (u64)m0 * K;
    const u64 boff0 = (u64)n0 * K;
    const int NC = K >> 5;

    // async fill of one stage: 3 tiles x 128 rows x 32 h16 (4x16B/row)
    auto fill = [&](int stage, int c) {
        const uint32_t sbase = sb + stage * STGB;
        const u64 ka = aoff0 + c * 32;
        const u64 kb = boff0 + c * 32;
#pragma unroll
        for (int j = 0; j < 6; ++j) {
            const int i   = tid + j * 256;
            const int t   = i >> 9;                  // 0:Ah 1:Al 2:B
            const int row = (i >> 2) & 127;
            const int ch  = i & 3;
            const h16* g  = (t == 0) ? Ah : (t == 1) ? Al : B;
            const u64 base = (t < 2) ? ka : kb;
            const uint32_t dst = sbase + (t * TSZ + row * LDSX + ch * 8) * 2;
            cp16(dst, g + base + (u64)row * K + ch * 8);
        }
    };

    float acc[4][4][4];
#pragma unroll
    for (int a = 0; a < 4; ++a)
#pragma unroll
        for (int b = 0; b < 4; ++b)
#pragma unroll
            for (int d = 0; d < 4; ++d) acc[a][b][d] = 0.f;

    // prologue: fill first 3 stages
#pragma unroll
    for (int p = 0; p < NSTG - 1; ++p) {
        if (p < NC) fill(p, p);
        cp_commit();
    }

    // ldmatrix lane addressing
    const int a_row = lane & 15;
    const int a_kof = (lane >> 4) * 8;
    const int b_row = (lane & 7) + ((lane >> 4) & 1) * 8;
    const int b_kof = ((lane >> 3) & 1) * 8;

    for (int c = 0; c < NC; ++c) {
        cp_wait<NSTG - 2>();
        __syncthreads();
        if (c + NSTG - 1 < NC) fill((c + NSTG - 1) & (NSTG - 1), c + NSTG - 1);
        cp_commit();

        const uint32_t st = sb + (c & (NSTG - 1)) * STGB;
#pragma unroll
        for (int ks = 0; ks < 2; ++ks) {
            const int k0s = ks * 16;
            uint32_t aH[4][4], aL[4][4], bS[2][4];
#pragma unroll
            for (int mi = 0; mi < 4; ++mi) {
                const uint32_t ra = st + ((wm + mi * 16 + a_row) * LDSX + k0s + a_kof) * 2;
                ldm4(aH[mi], ra);
                ldm4(aL[mi], ra + TSZ * 2);
            }
#pragma unroll
            for (int np = 0; np < 2; ++np) {
                const uint32_t rb = st + (2 * TSZ + (wn + np * 16 + b_row) * LDSX + k0s + b_kof) * 2;
                ldm4(bS[np], rb);
            }
#pragma unroll
            for (int mi = 0; mi < 4; ++mi) {
#pragma unroll
                for (int ni = 0; ni < 4; ++ni) {
                    const uint32_t b0 = bS[ni >> 1][(ni & 1) * 2];
                    const uint32_t b1 = bS[ni >> 1][(ni & 1) * 2 + 1];
                    mma_f16(acc[mi][ni], aH[mi], b0, b1);
                    mma_f16(acc[mi][ni], aL[mi], b0, b1);
                }
            }
        }
    }

    // ---- epilogue
    const int er = lane >> 2;
    const int ec = (lane & 3) * 2;
#pragma unroll
    for (int mi = 0; mi < 4; ++mi) {
#pragma unroll
        for (int ni = 0; ni < 4; ++ni) {
            const int m = m0 + wm + mi * 16 + er;
            const int n = n0 + wn + ni * 8 + ec;
            const float* ac = acc[mi][ni];
            if (mode == 0) {
                if (n < Nw) {
                    const float b0 = bias[n], b1 = bias[n + 1];
                    float2 o0 = make_float2(ac[0] + b0, ac[1] + b1);
                    float2 o1 = make_float2(ac[2] + b0, ac[3] + b1);
                    *(float2*)&C[(u64)m * Nw + n]       = o0;
                    *(float2*)&C[(u64)(m + 8) * Nw + n] = o1;
                }
            } else if (mode == 1) {
                float2 mk0 = *(const float2*)&mask[(u64)m * SS + n];
                float2 mk1 = *(const float2*)&mask[(u64)(m + 8) * SS + n];
                float2 o0 = make_float2(ac[0] * SCALE + mk0.x, ac[1] * SCALE + mk0.y);
                float2 o1 = make_float2(ac[2] * SCALE + mk1.x, ac[3] * SCALE + mk1.y);
                *(float2*)&C[(u64)m * SS + n]       = o0;
                *(float2*)&C[(u64)(m + 8) * SS + n] = o1;
            } else {
                const int b = z >> 4, h = z & 15;
                const u64 r0o = (u64)(b * SS + m)     * (NH * VHD) + (u64)h * VHD + n;
                const u64 r1o = (u64)(b * SS + m + 8) * (NH * VHD) + (u64)h * VHD + n;
#pragma unroll
                for (int d = 0; d < 2; ++d) {
                    float v0 = ac[d], v1 = ac[2 + d];
                    h16 h0 = __float2half_rn(v0);
                    h16 h1 = __float2half_rn(v1);
                    Oh[r0o + d] = h0; Ol[r0o + d] = __float2half_rn(v0 - __half2float(h0));
                    Oh[r1o + d] = h1; Ol[r1o + d] = __float2half_rn(v1 - __half2float(h1));
                }
            }
        }
    }
}

// ------------------------------------------------------------------
// elementwise kernels
// ------------------------------------------------------------------
__global__ void k_split(const float* __restrict__ x, h16* __restrict__ h,
                        h16* __restrict__ l, int n)
{
    int i = blockIdx.x * 256 + threadIdx.x;
    if (i >= n) return;
    float v = x[i];
    h16 hv = __float2half_rn(v);
    h[i] = hv;
    l[i] = __float2half_rn(v - __half2float(hv));
}

__global__ void k_split1(const float* __restrict__ x, h16* __restrict__ o, int n)
{
    int i = blockIdx.x * 256 + threadIdx.x;
    if (i >= n) return;
    o[i] = __float2half_rn(x[i]);
}

__global__ void k_split1_pad(const float* __restrict__ x, h16* __restrict__ o,
                             int rows_src, int cols, int rows_dst)
{
    int i = blockIdx.x * 256 + threadIdx.x;
    if (i >= rows_dst * cols) return;
    int r = i / cols;
    o[i] = __float2half_rn((r < rows_src) ? x[i] : 0.f);
}

__global__ void __launch_bounds__(256)
k_rmsnorm(const float* __restrict__ X, const float* __restrict__ w,
          h16* __restrict__ Yh, h16* __restrict__ Yl,
          int W, int inStride, int outStride)
{
    int row = blockIdx.x;
    const float* x = X + (u64)row * inStride;
    float s = 0.f;
    for (int i = threadIdx.x; i < W; i += 256) { float v = x[i]; s += v * v; }
    __shared__ float red[256];
    red[threadIdx.x] = s; __syncthreads();
    for (int off = 128; off > 0; off >>= 1) {
        if (threadIdx.x < off) red[threadIdx.x] += red[threadIdx.x + off];
        __syncthreads();
    }
    float r = rsqrtf(red[0] / (float)W + 1e-6f);
    h16* yh = Yh + (u64)row * outStride;
    h16* yl = Yl + (u64)row * outStride;
    for (int i = threadIdx.x; i < W; i += 256) {
        float v = w[i] * (x[i] * r);
        h16 hv = __float2half_rn(v);
        yh[i] = hv;
        yl[i] = __float2half_rn(v - __half2float(hv));
    }
}

__device__ __forceinline__ float rope_val(float x1, float x2, int s, int i, int odd)
{
    float inv = powf(10000.f, -(float)(2 * i) / (float)ROPEd);
    float sn, cs;
    sincosf((float)s * inv, &sn, &cs);
    return odd ? (x1 * sn + x2 * cs) : (x1 * cs - x2 * sn);
}
__device__ __forceinline__ void wr_split(h16* H, h16* L, u64 o, float v)
{
    h16 hv = __float2half_rn(v);
    H[o] = hv;
    L[o] = __float2half_rn(v - __half2float(hv));
}

__global__ void k_prep_q()
{
    int idx = blockIdx.x * blockDim.x + threadIdx.x;
    if (idx >= BB * SS * NH * QKD) return;
    int d = idx % QKD;
    int h = (idx / QKD) % NH;
    int s = (idx / (QKD * NH)) % SS;
    int b =  idx / (QKD * NH * SS);
    const float* qrow = g_q + (u64)(b * SS + s) * HID + h * QKD;
    float val;
    if (d < NOPEd) val = qrow[d];
    else {
        int i = (d - NOPEd) >> 1;
        val = rope_val(qrow[NOPEd + 2 * i], qrow[NOPEd + 2 * i + 1], s, i, (d - NOPEd) & 1);
    }
    wr_split(g_Qh_h, g_Qh_l, ((u64)(b * NH + h) * SS + s) * QKD + d, val);
}

__global__ void k_prep_k()
{
    int idx = blockIdx.x * blockDim.x + threadIdx.x;
    if (idx >= BB * SS * NH * QKD) return;
    int d = idx % QKD;
    int h = (idx / QKD) % NH;
    int s = (idx / (QKD * NH)) % SS;
    int b =  idx / (QKD * NH * SS);
    float val;
    if (d < NOPEd) {
        val = g_kvb[(u64)(b * SS + s) * (NH * KVOUT) + h * KVOUT + d];
    } else {
        int i = (d - NOPEd) >> 1;
        const float* kr = g_kv + (u64)(b * SS + s) * KVA_N + KVL;
        val = rope_val(kr[2 * i], kr[2 * i + 1], s, i, (d - NOPEd) & 1);
    }
    g_Kh[((u64)(b * NH + h) * SS + s) * QKD + d] = __float2half_rn(val);
}

__global__ void k_prep_v()   // V transposed: [b][h][d][t], single fp16
{
    int idx = blockIdx.x * blockDim.x + threadIdx.x;
    if (idx >= BB * NH * VHD * SS) return;
    int s = idx % SS;
    int d = (idx / SS) % VHD;
    int h = (idx / (SS * VHD)) % NH;
    int b =  idx / (SS * VHD * NH);
    float v = g_kvb[(u64)(b * SS + s) * (NH * KVOUT) + h * KVOUT + NOPEd + d];
    g_Vt[idx] = __float2half_rn(v);
}

__global__ void __launch_bounds__(256)
k_softmax()
{
    const float* p = g_sc + (u64)blockIdx.x * SS;
    int t = threadIdx.x;
    float4 v = *(const float4*)&p[t * 4];
    __shared__ float red[256];
    float mx = fmaxf(fmaxf(v.x, v.y), fmaxf(v.z, v.w));
    red[t] = mx; __syncthreads();
    for (int off = 128; off > 0; off >>= 1) {
        if (t < off) red[t] = fmaxf(red[t], red[t + off]);
        __syncthreads();
    }
    mx = red[0]; __syncthreads();
    v.x = expf(v.x - mx); v.y = expf(v.y - mx);
    v.z = expf(v.z - mx); v.w = expf(v.w - mx);
    red[t] = v.x + v.y + v.z + v.w; __syncthreads();
    for (int off = 128; off > 0; off >>= 1) {
        if (t < off) red[t] += red[t + off];
        __syncthreads();
    }
    float inv = 1.0f / red[0];
    u64 o = (u64)blockIdx.x * SS + t * 4;
    wr_split(g_P_h, g_P_l, o + 0, v.x * inv);
    wr_split(g_P_h, g_P_l, o + 1, v.y * inv);
    wr_split(g_P_h, g_P_l, o + 2, v.z * inv);
    wr_split(g_P_h, g_P_l, o + 3, v.w * inv);
}

// ------------------------------------------------------------------
// launch
// ------------------------------------------------------------------
static inline void* sym(const void* s) { void* p; cudaGetSymbolAddress(&p, s); return p; }

extern "C" void kernel_launch(void* const* d_in, const int* in_sizes, int n_in,
                              void* d_out, int out_size)
{
    const float* hs        = (const float*)d_in[0];
    const float* mask      = (const float*)d_in[1];
    const float* wq_a_w    = (const float*)d_in[2];
    const float* wq_a_b    = (const float*)d_in[3];
    const float* q_norm_w  = (const float*)d_in[4];
    const float* wq_b_w    = (const float*)d_in[5];
    const float* wq_b_b    = (const float*)d_in[6];
    const float* wkv_a_w   = (const float*)d_in[7];
    const float* wkv_a_b   = (const float*)d_in[8];
    const float* kv_norm_w = (const float*)d_in[9];
    const float* wkv_b_w   = (const float*)d_in[10];
    const float* wkv_b_b   = (const float*)d_in[11];
    const float* wo_w      = (const float*)d_in[12];
    const float* wo_b      = (const float*)d_in[13];
    float* out = (float*)d_out;

    static int smem_set = 0;
    if (!smem_set) {
        cudaFuncSetAttribute(k_mma, cudaFuncAttributeMaxDynamicSharedMemorySize, SMEM_BYTES);
        smem_set = 1;
    }

    h16 *hs_h=(h16*)sym(g_hs_h), *hs_l=(h16*)sym(g_hs_l);
    h16 *wqa=(h16*)sym(g_wqa), *wqb=(h16*)sym(g_wqb);
    h16 *wkva=(h16*)sym(g_wkva), *wkvb=(h16*)sym(g_wkvb), *wo=(h16*)sym(g_wo);
    float *qlat=(float*)sym(g_qlat), *q=(float*)sym(g_q);
    h16 *qln_h=(h16*)sym(g_qln_h), *qln_l=(h16*)sym(g_qln_l);
    float *kv=(float*)sym(g_kv), *kvb=(float*)sym(g_kvb);
    h16 *kvln_h=(h16*)sym(g_kvln_h), *kvln_l=(h16*)sym(g_kvln_l);
    h16 *Qh_h=(h16*)sym(g_Qh_h), *Qh_l=(h16*)sym(g_Qh_l);
    h16 *Kh=(h16*)sym(g_Kh), *Vt=(h16*)sym(g_Vt);
    float *sc=(float*)sym(g_sc);
    h16 *P_h=(h16*)sym(g_P_h), *P_l=(h16*)sym(g_P_l);
    h16 *at_h=(h16*)sym(g_at_h), *at_l=(h16*)sym(g_at_l);

    // ---- splits of inputs/weights
    k_split <<<(NT*HID + 255)/256, 256>>>(hs, hs_h, hs_l, NT*HID);
    k_split1<<<(QL*HID + 255)/256, 256>>>(wq_a_w, wqa, QL*HID);
    k_split1<<<(HID*QL + 255)/256, 256>>>(wq_b_w, wqb, HID*QL);
    k_split1_pad<<<(KVA_NP*HID + 255)/256, 256>>>(wkv_a_w, wkva, KVA_N, HID, KVA_NP);
    k_split1<<<(NH*KVOUT*KVL + 255)/256, 256>>>(wkv_b_w, wkvb, NH*KVOUT*KVL);
    k_split1<<<(HID*NH*VHD + 255)/256, 256>>>(wo_w, wo, HID*NH*VHD);

    // ---- q path
    k_mma<<<dim3(QL/128, NT/128, 1), 256, SMEM_BYTES>>>(
        hs_h, hs_l, wqa, qlat, wq_a_b, nullptr, nullptr, nullptr,
        NT, QL, HID, QL, 0);
    k_rmsnorm<<<NT, 256>>>(qlat, q_norm_w, qln_h, qln_l, QL, QL, QL);
    k_mma<<<dim3(HID/128, NT/128, 1), 256, SMEM_BYTES>>>(
        qln_h, qln_l, wqb, q, wq_b_b, nullptr, nullptr, nullptr,
        NT, HID, QL, HID, 0);

    // ---- kv path
    k_mma<<<dim3(KVA_NP/128, NT/128, 1), 256, SMEM_BYTES>>>(
        hs_h, hs_l, wkva, kv, wkv_a_b, nullptr, nullptr, nullptr,
        NT, KVA_NP, HID, KVA_N, 0);
    k_rmsnorm<<<NT, 256>>>(kv, kv_norm_w, kvln_h, kvln_l, KVL, KVA_N, KVL);
    k_mma<<<dim3(NH*KVOUT/128, NT/128, 1), 256, SMEM_BYTES>>>(
        kvln_h, kvln_l, wkvb, kvb, wkv_b_b, nullptr, nullptr, nullptr,
        NT, NH*KVOUT, KVL, NH*KVOUT, 0);

    // ---- head gather + rope + transpose
    k_prep_q<<<(BB*SS*NH*QKD + 255)/256, 256>>>();
    k_prep_k<<<(BB*SS*NH*QKD + 255)/256, 256>>>();
    k_prep_v<<<(BB*NH*VHD*SS + 255)/256, 256>>>();

    // ---- attention
    k_mma<<<dim3(SS/128, SS/128, BB*NH), 256, SMEM_BYTES>>>(
        Qh_h, Qh_l, Kh, sc, nullptr, mask, nullptr, nullptr,
        SS, SS, QKD, SS, 1);
    k_softmax<<<BB*NH*SS, 256>>>();
    k_mma<<<dim3(VHD/128, SS/128, BB*NH), 256, SMEM_BYTES>>>(
        P_h, P_l, Vt, nullptr, nullptr, nullptr, at_h, at_l,
        SS, VHD, SS, VHD, 2);

    // ---- output projection
    k_mma<<<dim3(HID/128, NT/128, 1), 256, SMEM_BYTES>>>(
        at_h, at_l, wo, out, wo_b, nullptr, nullptr, nullptr,
        NT, HID, NH*VHD, HID, 0);
}

// round 9
// speedup vs baseline: 1.2146x; 1.2146x over previous
#include <cuda_runtime.h>
#include <cuda_fp16.h>
#include <math.h>
#include <stdint.h>

typedef unsigned long long u64;
typedef __half h16;

#define BB 2
#define SS 1024
#define HID 3072
#define NH 16
#define QL 1536
#define KVL 512
#define NOPEd 128
#define ROPEd 64
#define QKD 192
#define VHD 128
#define NT (BB*SS)
#define KVOUT 256
#define QKVN 2176          /* QL + KVL + ROPE padded to 17*128 */
#define QKVW 2112          /* valid columns: QL + KVL + ROPE */
#define SCALE 0.07216878364870323f

// ------------------------------------------------------------------
// scratch (device globals)
// ------------------------------------------------------------------
#define AL __align__(256)
__device__ AL h16   g_hs_h [NT*HID],      g_hs_l [NT*HID];
__device__ AL h16   g_wqkva[QKVN*HID];            /* wq_a ⊕ wkv_a ⊕ 0 */
__device__ AL float g_bqkva[QKVN];
__device__ AL h16   g_wqb [HID*QL];
__device__ AL h16   g_wkvb[NH*KVOUT*KVL];
__device__ AL h16   g_wo  [HID*NH*VHD];
__device__ AL float g_qkv [NT*QKVN];              /* q_lat | kv_lat | k_rope */
__device__ AL h16   g_qln_h[NT*QL],       g_qln_l[NT*QL];
__device__ AL float g_q   [NT*HID];
__device__ AL h16   g_kvln_h[NT*KVL],     g_kvln_l[NT*KVL];
__device__ AL float g_kvb [NT*NH*KVOUT];
__device__ AL h16   g_Qh_h[(u64)BB*NH*SS*QKD], g_Qh_l[(u64)BB*NH*SS*QKD];
__device__ AL h16   g_Kh  [(u64)BB*NH*SS*QKD];
__device__ AL h16   g_Vt  [(u64)BB*NH*VHD*SS];    /* [b][h][d][t] */
__device__ AL float g_sc  [(u64)BB*NH*SS*SS];
__device__ AL h16   g_P_h [(u64)BB*NH*SS*SS],  g_P_l [(u64)BB*NH*SS*SS];
__device__ AL h16   g_at_h[NT*NH*VHD],    g_at_l[NT*NH*VHD];

// ------------------------------------------------------------------
// PTX helpers (sm_80+ ISA: cp.async / ldmatrix / mma.sync fp16)
// ------------------------------------------------------------------
__device__ __forceinline__ uint32_t smem_u32(const void* p) {
    uint32_t a;
    asm("{ .reg .u64 t; cvta.to.shared.u64 t, %1; cvt.u32.u64 %0, t; }" : "=r"(a) : "l"(p));
    return a;
}
__device__ __forceinline__ void cp16(uint32_t dst, const void* src) {
    asm volatile("cp.async.cg.shared.global [%0], [%1], 16;" :: "r"(dst), "l"(src));
}
__device__ __forceinline__ void cp_commit() {
    asm volatile("cp.async.commit_group;" ::: "memory");
}
template<int N> __device__ __forceinline__ void cp_wait() {
    asm volatile("cp.async.wait_group %0;" :: "n"(N) : "memory");
}
__device__ __forceinline__ void ldm4(uint32_t* r, uint32_t addr) {
    asm volatile("ldmatrix.sync.aligned.m8n8.x4.shared.b16 {%0,%1,%2,%3}, [%4];"
        : "=r"(r[0]), "=r"(r[1]), "=r"(r[2]), "=r"(r[3]) : "r"(addr));
}
__device__ __forceinline__ void mma_f16(float* c, const uint32_t* a, uint32_t b0, uint32_t b1) {
    asm volatile(
        "mma.sync.aligned.m16n8k16.row.col.f32.f16.f16.f32 "
        "{%0,%1,%2,%3}, {%4,%5,%6,%7}, {%8,%9}, {%0,%1,%2,%3};"
        : "+f"(c[0]), "+f"(c[1]), "+f"(c[2]), "+f"(c[3])
        : "r"(a[0]), "r"(a[1]), "r"(a[2]), "r"(a[3]), "r"(b0), "r"(b1));
}

// ------------------------------------------------------------------
// fp16 2-term split GEMM: C[m][n] = sum_k (Ah+Al)[m][k]*B[n][k]
// tile 128x128, BK=32, 256 threads (2x4 warps, 64x32 warp tile),
// 4-stage cp.async pipeline, padded smem stride 40 h16 (80 B).
// mode 0: C = acc + bias (float out, stride ldc, store-guard n<Nw)
// mode 1: scores: acc*SCALE + mask (z = bh); causal tile-skip bx>by
// mode 2: PV: split to Oh/Ol with head scatter (z = bh); causal NC cap
// ------------------------------------------------------------------
#define LDSX 40
#define TSZ  (128*LDSX)
#define STGB (3*TSZ*2)
#define NSTG 4
#define SMEM_BYTES (NSTG*STGB)   /* 122880 bytes */

__global__ void __launch_bounds__(256, 1)
k_mma(const h16* __restrict__ Ah, const h16* __restrict__ Al,
      const h16* __restrict__ B,
      float* __restrict__ C, const float* __restrict__ bias,
      const float* __restrict__ mask,
      h16* __restrict__ Oh, h16* __restrict__ Ol,
      int M, int N, int K, int Nw, int ldc, int mode)
{
    const int z  = blockIdx.z;
    const int m0 = blockIdx.y * 128, n0 = blockIdx.x * 128;

    if (mode == 1 && n0 > m0 + 127) return;   // fully-masked causal tile

    extern __shared__ h16 sm[];
    const uint32_t sb = smem_u32(sm);

    const int tid  = threadIdx.x;
    const int wid  = tid >> 5, lane = tid & 31;
    const int wm   = (wid & 1) * 64;
    const int wn   = (wid >> 1) * 32;

    if (mode == 1) {
        Ah += (u64)z*SS*QKD; Al += (u64)z*SS*QKD;
        B  += (u64)z*SS*QKD;
        C  += (u64)z*SS*SS;
    } else if (mode == 2) {
        Ah += (u64)z*SS*SS;  Al += (u64)z*SS*SS;
        B  += (u64)z*VHD*SS;
    }

    const u64 aoff0 = (u64)m0 * K;
    const u64 boff0 = (u64)n0 * K;
    int NC = K >> 5;
    if (mode == 2) { int nc = (m0 >> 5) + 4; if (nc < NC) NC = nc; }  // P zero beyond diag tile

    auto fill = [&](int stage, int c) {
        const uint32_t sbase = sb + stage * STGB;
        const u64 ka = aoff0 + c * 32;
        const u64 kb = boff0 + c * 32;
#pragma unroll
        for (int j = 0; j < 6; ++j) {
            const int i   = tid + j * 256;
            const int t   = i >> 9;
            const int row = (i >> 2) & 127;
            const int ch  = i & 3;
            const h16* g  = (t == 0) ? Ah : (t == 1) ? Al : B;
            const u64 base = (t < 2) ? ka : kb;
            const uint32_t dst = sbase + (t * TSZ + row * LDSX + ch * 8) * 2;
            cp16(dst, g + base + (u64)row * K + ch * 8);
        }
    };

    float acc[4][4][4];
#pragma unroll
    for (int a = 0; a < 4; ++a)
#pragma unroll
        for (int b = 0; b < 4; ++b)
#pragma unroll
            for (int d = 0; d < 4; ++d) acc[a][b][d] = 0.f;

#pragma unroll
    for (int p = 0; p < NSTG - 1; ++p) {
        if (p < NC) fill(p, p);
        cp_commit();
    }

    const int a_row = lane & 15;
    const int a_kof = (lane >> 4) * 8;
    const int b_row = (lane & 7) + ((lane >> 4) & 1) * 8;
    const int b_kof = ((lane >> 3) & 1) * 8;

    for (int c = 0; c < NC; ++c) {
        cp_wait<NSTG - 2>();
        __syncthreads();
        if (c + NSTG - 1 < NC) fill((c + NSTG - 1) & (NSTG - 1), c + NSTG - 1);
        cp_commit();

        const uint32_t st = sb + (c & (NSTG - 1)) * STGB;
#pragma unroll
        for (int ks = 0; ks < 2; ++ks) {
            const int k0s = ks * 16;
            uint32_t aH[4][4], aL[4][4], bS[2][4];
#pragma unroll
            for (int mi = 0; mi < 4; ++mi) {
                const uint32_t ra = st + ((wm + mi * 16 + a_row) * LDSX + k0s + a_kof) * 2;
                ldm4(aH[mi], ra);
                ldm4(aL[mi], ra + TSZ * 2);
            }
#pragma unroll
            for (int np = 0; np < 2; ++np) {
                const uint32_t rb = st + (2 * TSZ + (wn + np * 16 + b_row) * LDSX + k0s + b_kof) * 2;
                ldm4(bS[np], rb);
            }
#pragma unroll
            for (int mi = 0; mi < 4; ++mi) {
#pragma unroll
                for (int ni = 0; ni < 4; ++ni) {
                    const uint32_t b0 = bS[ni >> 1][(ni & 1) * 2];
                    const uint32_t b1 = bS[ni >> 1][(ni & 1) * 2 + 1];
                    mma_f16(acc[mi][ni], aH[mi], b0, b1);
                    mma_f16(acc[mi][ni], aL[mi], b0, b1);
                }
            }
        }
    }

    const int er = lane >> 2;
    const int ec = (lane & 3) * 2;
#pragma unroll
    for (int mi = 0; mi < 4; ++mi) {
#pragma unroll
        for (int ni = 0; ni < 4; ++ni) {
            const int m = m0 + wm + mi * 16 + er;
            const int n = n0 + wn + ni * 8 + ec;
            const float* ac = acc[mi][ni];
            if (mode == 0) {
                if (n < Nw) {
                    const float b0 = bias[n], b1 = bias[n + 1];
                    float2 o0 = make_float2(ac[0] + b0, ac[1] + b1);
                    float2 o1 = make_float2(ac[2] + b0, ac[3] + b1);
                    *(float2*)&C[(u64)m * ldc + n]       = o0;
                    *(float2*)&C[(u64)(m + 8) * ldc + n] = o1;
                }
            } else if (mode == 1) {
                float2 mk0 = *(const float2*)&mask[(u64)m * SS + n];
                float2 mk1 = *(const float2*)&mask[(u64)(m + 8) * SS + n];
                float2 o0 = make_float2(ac[0] * SCALE + mk0.x, ac[1] * SCALE + mk0.y);
                float2 o1 = make_float2(ac[2] * SCALE + mk1.x, ac[3] * SCALE + mk1.y);
                *(float2*)&C[(u64)m * SS + n]       = o0;
                *(float2*)&C[(u64)(m + 8) * SS + n] = o1;
            } else {
                const int b = z >> 4, h = z & 15;
                const u64 r0o = (u64)(b * SS + m)     * (NH * VHD) + (u64)h * VHD + n;
                const u64 r1o = (u64)(b * SS + m + 8) * (NH * VHD) + (u64)h * VHD + n;
#pragma unroll
                for (int d = 0; d < 2; ++d) {
                    float v0 = ac[d], v1 = ac[2 + d];
                    h16 h0 = __float2half_rn(v0);
                    h16 h1 = __float2half_rn(v1);
                    Oh[r0o + d] = h0; Ol[r0o + d] = __float2half_rn(v0 - __half2float(h0));
                    Oh[r1o + d] = h1; Ol[r1o + d] = __float2half_rn(v1 - __half2float(h1));
                }
            }
        }
    }
}

// ------------------------------------------------------------------
// elementwise kernels
// ------------------------------------------------------------------
__global__ void k_split(const float* __restrict__ x, h16* __restrict__ h,
                        h16* __restrict__ l, int n)
{
    int i = blockIdx.x * 256 + threadIdx.x;
    if (i >= n) return;
    float v = x[i];
    h16 hv = __float2half_rn(v);
    h[i] = hv;
    l[i] = __float2half_rn(v - __half2float(hv));
}

__global__ void k_split1(const float* __restrict__ x, h16* __restrict__ o, int n)
{
    int i = blockIdx.x * 256 + threadIdx.x;
    if (i >= n) return;
    o[i] = __float2half_rn(x[i]);
}

// pack wq_a (1536 rows) + wkv_a (576 rows) + zeros into [2176, 3072] fp16
__global__ void k_pack_wa(const float* __restrict__ wqa, const float* __restrict__ wkva)
{
    int c = blockIdx.x * 256 + threadIdx.x;   // 0..3071
    int r = blockIdx.y;                        // 0..2175
    if (c >= HID) return;
    float v = 0.f;
    if (r < QL)        v = wqa[(u64)r * HID + c];
    else if (r < QKVW) v = wkva[(u64)(r - QL) * HID + c];
    g_wqkva[(u64)r * HID + c] = __float2half_rn(v);
}

__global__ void k_pack_bias(const float* __restrict__ bqa, const float* __restrict__ bkva)
{
    int i = blockIdx.x * 256 + threadIdx.x;
    if (i >= QKVN) return;
    float v = 0.f;
    if (i < QL)        v = bqa[i];
    else if (i < QKVW) v = bkva[i - QL];
    g_bqkva[i] = v;
}

__global__ void __launch_bounds__(256)
k_rmsnorm(const float* __restrict__ X, const float* __restrict__ w,
          h16* __restrict__ Yh, h16* __restrict__ Yl,
          int W, int inStride, int outStride)
{
    int row = blockIdx.x;
    const float* x = X + (u64)row * inStride;
    float s = 0.f;
    for (int i = threadIdx.x; i < W; i += 256) { float v = x[i]; s += v * v; }
    __shared__ float red[256];
    red[threadIdx.x] = s; __syncthreads();
    for (int off = 128; off > 0; off >>= 1) {
        if (threadIdx.x < off) red[threadIdx.x] += red[threadIdx.x + off];
        __syncthreads();
    }
    float r = rsqrtf(red[0] / (float)W + 1e-6f);
    h16* yh = Yh + (u64)row * outStride;
    h16* yl = Yl + (u64)row * outStride;
    for (int i = threadIdx.x; i < W; i += 256) {
        float v = w[i] * (x[i] * r);
        h16 hv = __float2half_rn(v);
        yh[i] = hv;
        yl[i] = __float2half_rn(v - __half2float(hv));
    }
}

__device__ __forceinline__ float rope_val(float x1, float x2, int s, int i, int odd)
{
    float inv = powf(10000.f, -(float)(2 * i) / (float)ROPEd);
    float sn, cs;
    sincosf((float)s * inv, &sn, &cs);
    return odd ? (x1 * sn + x2 * cs) : (x1 * cs - x2 * sn);
}
__device__ __forceinline__ void wr_split(h16* H, h16* L, u64 o, float v)
{
    h16 hv = __float2half_rn(v);
    H[o] = hv;
    L[o] = __float2half_rn(v - __half2float(hv));
}

__global__ void k_prep_q()
{
    int idx = blockIdx.x * blockDim.x + threadIdx.x;
    if (idx >= BB * SS * NH * QKD) return;
    int d = idx % QKD;
    int h = (idx / QKD) % NH;
    int s = (idx / (QKD * NH)) % SS;
    int b =  idx / (QKD * NH * SS);
    const float* qrow = g_q + (u64)(b * SS + s) * HID + h * QKD;
    float val;
    if (d < NOPEd) val = qrow[d];
    else {
        int i = (d - NOPEd) >> 1;
        val = rope_val(qrow[NOPEd + 2 * i], qrow[NOPEd + 2 * i + 1], s, i, (d - NOPEd) & 1);
    }
    wr_split(g_Qh_h, g_Qh_l, ((u64)(b * NH + h) * SS + s) * QKD + d, val);
}

__global__ void k_prep_k()
{
    int idx = blockIdx.x * blockDim.x + threadIdx.x;
    if (idx >= BB * SS * NH * QKD) return;
    int d = idx % QKD;
    int h = (idx / QKD) % NH;
    int s = (idx / (QKD * NH)) % SS;
    int b =  idx / (QKD * NH * SS);
    float val;
    if (d < NOPEd) {
        val = g_kvb[(u64)(b * SS + s) * (NH * KVOUT) + h * KVOUT + d];
    } else {
        int i = (d - NOPEd) >> 1;
        const float* kr = g_qkv + (u64)(b * SS + s) * QKVN + (QL + KVL);  // k_rope cols
        val = rope_val(kr[2 * i], kr[2 * i + 1], s, i, (d - NOPEd) & 1);
    }
    g_Kh[((u64)(b * NH + h) * SS + s) * QKD + d] = __float2half_rn(val);
}

__global__ void k_prep_v()   // V transposed: [b][h][d][t], single fp16
{
    int idx = blockIdx.x * blockDim.x + threadIdx.x;
    if (idx >= BB * NH * VHD * SS) return;
    int s = idx % SS;
    int d = (idx / SS) % VHD;
    int h = (idx / (SS * VHD)) % NH;
    int b =  idx / (SS * VHD * NH);
    float v = g_kvb[(u64)(b * SS + s) * (NH * KVOUT) + h * KVOUT + NOPEd + d];
    g_Vt[idx] = __float2half_rn(v);
}

// causal softmax: row m only has valid logits for t < L = (floor(m/128)+1)*128
// (diag tile fully computed with mask applied; tiles beyond never written/read)
__global__ void __launch_bounds__(256)
k_softmax()
{
    const int m = blockIdx.x & (SS - 1);
    const int L = (((m >> 7) + 1) << 7);
    const float* p = g_sc + (u64)blockIdx.x * SS;
    int t = threadIdx.x;
    const bool act = (t * 4) < L;
    float4 v = act ? *(const float4*)&p[t * 4] : make_float4(-1e30f, -1e30f, -1e30f, -1e30f);
    __shared__ float red[256];
    float mx = fmaxf(fmaxf(v.x, v.y), fmaxf(v.z, v.w));
    red[t] = mx; __syncthreads();
    for (int off = 128; off > 0; off >>= 1) {
        if (t < off) red[t] = fmaxf(red[t], red[t + off]);
        __syncthreads();
    }
    mx = red[0]; __syncthreads();
    v.x = expf(v.x - mx); v.y = expf(v.y - mx);
    v.z = expf(v.z - mx); v.w = expf(v.w - mx);
    red[t] = act ? (v.x + v.y + v.z + v.w) : 0.f;
    __syncthreads();
    for (int off = 128; off > 0; off >>= 1) {
        if (t < off) red[t] += red[t + off];
        __syncthreads();
    }
    if (!act) return;
    float inv = 1.0f / red[0];
    u64 o = (u64)blockIdx.x * SS + t * 4;
    wr_split(g_P_h, g_P_l, o + 0, v.x * inv);
    wr_split(g_P_h, g_P_l, o + 1, v.y * inv);
    wr_split(g_P_h, g_P_l, o + 2, v.z * inv);
    wr_split(g_P_h, g_P_l, o + 3, v.w * inv);
}

// ------------------------------------------------------------------
// launch (two-stream fork/join, graph-capture-safe)
// ------------------------------------------------------------------
static inline void* sym(const void* s) { void* p; cudaGetSymbolAddress(&p, s); return p; }

extern "C" void kernel_launch(void* const* d_in, const int* in_sizes, int n_in,
                              void* d_out, int out_size)
{
    const float* hs        = (const float*)d_in[0];
    const float* mask      = (const float*)d_in[1];
    const float* wq_a_w    = (const float*)d_in[2];
    const float* wq_a_b    = (const float*)d_in[3];
    const float* q_norm_w  = (const float*)d_in[4];
    const float* wq_b_w    = (const float*)d_in[5];
    const float* wq_b_b    = (const float*)d_in[6];
    const float* wkv_a_w   = (const float*)d_in[7];
    const float* wkv_a_b   = (const float*)d_in[8];
    const float* kv_norm_w = (const float*)d_in[9];
    const float* wkv_b_w   = (const float*)d_in[10];
    const float* wkv_b_b   = (const float*)d_in[11];
    const float* wo_w      = (const float*)d_in[12];
    const float* wo_b      = (const float*)d_in[13];
    float* out = (float*)d_out;

    static bool init = false;
    static cudaStream_t s1;
    static cudaEvent_t e0, e_wqb, e_g13, e_kv;
    if (!init) {
        cudaFuncSetAttribute(k_mma, cudaFuncAttributeMaxDynamicSharedMemorySize, SMEM_BYTES);
        cudaStreamCreateWithFlags(&s1, cudaStreamNonBlocking);
        cudaEventCreateWithFlags(&e0,    cudaEventDisableTiming);
        cudaEventCreateWithFlags(&e_wqb, cudaEventDisableTiming);
        cudaEventCreateWithFlags(&e_g13, cudaEventDisableTiming);
        cudaEventCreateWithFlags(&e_kv,  cudaEventDisableTiming);
        init = true;
    }

    h16 *hs_h=(h16*)sym(g_hs_h), *hs_l=(h16*)sym(g_hs_l);
    h16 *wqkva=(h16*)sym(g_wqkva);
    float *bqkva=(float*)sym(g_bqkva);
    h16 *wqb=(h16*)sym(g_wqb), *wkvb=(h16*)sym(g_wkvb), *wo=(h16*)sym(g_wo);
    float *qkv=(float*)sym(g_qkv), *q=(float*)sym(g_q), *kvb=(float*)sym(g_kvb);
    h16 *qln_h=(h16*)sym(g_qln_h), *qln_l=(h16*)sym(g_qln_l);
    h16 *kvln_h=(h16*)sym(g_kvln_h), *kvln_l=(h16*)sym(g_kvln_l);
    h16 *Qh_h=(h16*)sym(g_Qh_h), *Qh_l=(h16*)sym(g_Qh_l);
    h16 *Kh=(h16*)sym(g_Kh), *Vt=(h16*)sym(g_Vt);
    float *sc=(float*)sym(g_sc);
    h16 *P_h=(h16*)sym(g_P_h), *P_l=(h16*)sym(g_P_l);
    h16 *at_h=(h16*)sym(g_at_h), *at_l=(h16*)sym(g_at_l);

    // fork: side stream does the weight splits for later GEMMs
    cudaEventRecord(e0, 0);
    cudaStreamWaitEvent(s1, e0, 0);
    k_split1<<<(HID*QL + 255)/256, 256, 0, s1>>>(wq_b_w, wqb, HID*QL);
    cudaEventRecord(e_wqb, s1);
    k_split1<<<(NH*KVOUT*KVL + 255)/256, 256, 0, s1>>>(wkv_b_w, wkvb, NH*KVOUT*KVL);
    k_split1<<<(HID*NH*VHD + 255)/256, 256, 0, s1>>>(wo_w, wo, HID*NH*VHD);

    // main stream: inputs for merged first GEMM
    k_split<<<(NT*HID + 255)/256, 256>>>(hs, hs_h, hs_l, NT*HID);
    k_pack_wa<<<dim3((HID + 255)/256, QKVN), 256>>>(wq_a_w, wkv_a_w);
    k_pack_bias<<<(QKVN + 255)/256, 256>>>(wq_a_b, wkv_a_b);

    // merged q_lat + kv_lat + k_rope projection: [NT, 2176] = hs @ [2176,3072]^T
    k_mma<<<dim3(QKVN/128, NT/128, 1), 256, SMEM_BYTES>>>(
        hs_h, hs_l, wqkva, qkv, bqkva, nullptr, nullptr, nullptr,
        NT, QKVN, HID, QKVW, QKVN, 0);
    cudaEventRecord(e_g13, 0);

    // kv chain on side stream (overlaps q chain below)
    cudaStreamWaitEvent(s1, e_g13, 0);
    k_rmsnorm<<<NT, 256, 0, s1>>>(qkv + QL, kv_norm_w, kvln_h, kvln_l, KVL, QKVN, KVL);
    k_mma<<<dim3(NH*KVOUT/128, NT/128, 1), 256, SMEM_BYTES, s1>>>(
        kvln_h, kvln_l, wkvb, kvb, wkv_b_b, nullptr, nullptr, nullptr,
        NT, NH*KVOUT, KVL, NH*KVOUT, NH*KVOUT, 0);
    k_prep_k<<<(BB*SS*NH*QKD + 255)/256, 256, 0, s1>>>();
    k_prep_v<<<(BB*NH*VHD*SS + 255)/256, 256, 0, s1>>>();
    cudaEventRecord(e_kv, s1);

    // q chain on main stream
    k_rmsnorm<<<NT, 256>>>(qkv, q_norm_w, qln_h, qln_l, QL, QKVN, QL);
    cudaStreamWaitEvent(0, e_wqb, 0);
    k_mma<<<dim3(HID/128, NT/128, 1), 256, SMEM_BYTES>>>(
        qln_h, qln_l, wqb, q, wq_b_b, nullptr, nullptr, nullptr,
        NT, HID, QL, HID, HID, 0);
    k_prep_q<<<(BB*SS*NH*QKD + 255)/256, 256>>>();

    // join kv chain, then attention (causal-aware)
    cudaStreamWaitEvent(0, e_kv, 0);
    k_mma<<<dim3(SS/128, SS/128, BB*NH), 256, SMEM_BYTES>>>(
        Qh_h, Qh_l, Kh, sc, nullptr, mask, nullptr, nullptr,
        SS, SS, QKD, SS, SS, 1);
    k_softmax<<<BB*NH*SS, 256>>>();
    k_mma<<<dim3(VHD/128, SS/128, BB*NH), 256, SMEM_BYTES>>>(
        P_h, P_l, Vt, nullptr, nullptr, nullptr, at_h, at_l,
        SS, VHD, SS, VHD, VHD, 2);

    // output projection (wo split finished on s1, upstream of e_kv)
    k_mma<<<dim3(HID/128, NT/128, 1), 256, SMEM_BYTES>>>(
        at_h, at_l, wo, out, wo_b, nullptr, nullptr, nullptr,
        NT, HID, NH*VHD, HID, HID, 0);
}

// round 12
// speedup vs baseline: 1.4005x; 1.1531x over previous
#include <cuda_runtime.h>
#include <cuda_fp16.h>
#include <math.h>
#include <stdint.h>

typedef unsigned long long u64;
typedef __half h16;

#define BB 2
#define SS 1024
#define HID 3072
#define NH 16
#define QL 1536
#define KVL 512
#define NOPEd 128
#define ROPEd 64
#define QKD 192
#define VHD 128
#define NT (BB*SS)
#define KVOUT 256
#define QKVN 2176
#define QKVW 2112
#define SCALE 0.07216878364870323f

// ------------------------------------------------------------------
// scratch (device globals)
// ------------------------------------------------------------------
#define AL __align__(256)
__device__ AL h16   g_hs_h [NT*HID],      g_hs_l [NT*HID];
__device__ AL h16   g_wqkva[QKVN*HID];
__device__ AL float g_bqkva[QKVN];
__device__ AL h16   g_wqb [HID*QL];
__device__ AL h16   g_wkvb[NH*KVOUT*KVL];
__device__ AL h16   g_wo  [HID*NH*VHD];
__device__ AL float g_qkv [NT*QKVN];
__device__ AL h16   g_qln_h[NT*QL],       g_qln_l[NT*QL];
__device__ AL float g_q   [NT*HID];
__device__ AL h16   g_kvln_h[NT*KVL],     g_kvln_l[NT*KVL];
__device__ AL float g_kvb [NT*NH*KVOUT];
__device__ AL h16   g_Qh_h[(u64)BB*NH*SS*QKD], g_Qh_l[(u64)BB*NH*SS*QKD];
__device__ AL h16   g_Kh  [(u64)BB*NH*SS*QKD];
__device__ AL h16   g_Vt  [(u64)BB*NH*VHD*SS];    /* [b][h][d][t] */
__device__ AL h16   g_at_h[NT*NH*VHD],    g_at_l[NT*NH*VHD];

// ------------------------------------------------------------------
// PTX helpers
// ------------------------------------------------------------------
__device__ __forceinline__ uint32_t smem_u32(const void* p) {
    uint32_t a;
    asm("{ .reg .u64 t; cvta.to.shared.u64 t, %1; cvt.u32.u64 %0, t; }" : "=r"(a) : "l"(p));
    return a;
}
__device__ __forceinline__ void cp16(uint32_t dst, const void* src) {
    asm volatile("cp.async.cg.shared.global [%0], [%1], 16;" :: "r"(dst), "l"(src));
}
__device__ __forceinline__ void cp_commit() {
    asm volatile("cp.async.commit_group;" ::: "memory");
}
template<int N> __device__ __forceinline__ void cp_wait() {
    asm volatile("cp.async.wait_group %0;" :: "n"(N) : "memory");
}
__device__ __forceinline__ void ldm4(uint32_t* r, uint32_t addr) {
    asm volatile("ldmatrix.sync.aligned.m8n8.x4.shared.b16 {%0,%1,%2,%3}, [%4];"
        : "=r"(r[0]), "=r"(r[1]), "=r"(r[2]), "=r"(r[3]) : "r"(addr));
}
__device__ __forceinline__ void mma_f16(float* c, const uint32_t* a, uint32_t b0, uint32_t b1) {
    asm volatile(
        "mma.sync.aligned.m16n8k16.row.col.f32.f16.f16.f32 "
        "{%0,%1,%2,%3}, {%4,%5,%6,%7}, {%8,%9}, {%0,%1,%2,%3};"
        : "+f"(c[0]), "+f"(c[1]), "+f"(c[2]), "+f"(c[3])
        : "r"(a[0]), "r"(a[1]), "r"(a[2]), "r"(a[3]), "r"(b0), "r"(b1));
}
__device__ __forceinline__ uint32_t pack2(float x, float y) {
    __half2 h = __floats2half2_rn(x, y);
    return *(uint32_t*)&h;
}

// ------------------------------------------------------------------
// fp16 2-term split GEMM (projections): C = (Ah+Al) @ B^T + bias
// ------------------------------------------------------------------
#define LDSX 40
#define TSZ  (128*LDSX)
#define STGB (3*TSZ*2)
#define NSTG 4
#define SMEM_BYTES (NSTG*STGB)

__global__ void __launch_bounds__(256, 1)
k_mma(const h16* __restrict__ Ah, const h16* __restrict__ Al,
      const h16* __restrict__ B,
      float* __restrict__ C, const float* __restrict__ bias,
      int M, int N, int K, int Nw, int ldc)
{
    extern __shared__ h16 sm[];
    const uint32_t sb = smem_u32(sm);
    const int tid  = threadIdx.x;
    const int wid  = tid >> 5, lane = tid & 31;
    const int wm   = (wid & 1) * 64;
    const int wn   = (wid >> 1) * 32;
    const int m0   = blockIdx.y * 128, n0 = blockIdx.x * 128;

    const u64 aoff0 = (u64)m0 * K;
    const u64 boff0 = (u64)n0 * K;
    const int NC = K >> 5;

    auto fill = [&](int stage, int c) {
        const uint32_t sbase = sb + stage * STGB;
        const u64 ka = aoff0 + c * 32;
        const u64 kb = boff0 + c * 32;
#pragma unroll
        for (int j = 0; j < 6; ++j) {
            const int i   = tid + j * 256;
            const int t   = i >> 9;
            const int row = (i >> 2) & 127;
            const int ch  = i & 3;
            const h16* g  = (t == 0) ? Ah : (t == 1) ? Al : B;
            const u64 base = (t < 2) ? ka : kb;
            const uint32_t dst = sbase + (t * TSZ + row * LDSX + ch * 8) * 2;
            cp16(dst, g + base + (u64)row * K + ch * 8);
        }
    };

    float acc[4][4][4];
#pragma unroll
    for (int a = 0; a < 4; ++a)
#pragma unroll
        for (int b = 0; b < 4; ++b)
#pragma unroll
            for (int d = 0; d < 4; ++d) acc[a][b][d] = 0.f;

#pragma unroll
    for (int p = 0; p < NSTG - 1; ++p) { if (p < NC) fill(p, p); cp_commit(); }

    const int a_row = lane & 15;
    const int a_kof = (lane >> 4) * 8;
    const int b_row = (lane & 7) + ((lane >> 4) & 1) * 8;
    const int b_kof = ((lane >> 3) & 1) * 8;

    for (int c = 0; c < NC; ++c) {
        cp_wait<NSTG - 2>();
        __syncthreads();
        if (c + NSTG - 1 < NC) fill((c + NSTG - 1) & (NSTG - 1), c + NSTG - 1);
        cp_commit();

        const uint32_t st = sb + (c & (NSTG - 1)) * STGB;
#pragma unroll
        for (int ks = 0; ks < 2; ++ks) {
            const int k0s = ks * 16;
            uint32_t aH[4][4], aL[4][4], bS[2][4];
#pragma unroll
            for (int mi = 0; mi < 4; ++mi) {
                const uint32_t ra = st + ((wm + mi * 16 + a_row) * LDSX + k0s + a_kof) * 2;
                ldm4(aH[mi], ra);
                ldm4(aL[mi], ra + TSZ * 2);
            }
#pragma unroll
            for (int np = 0; np < 2; ++np) {
                const uint32_t rb = st + (2 * TSZ + (wn + np * 16 + b_row) * LDSX + k0s + b_kof) * 2;
                ldm4(bS[np], rb);
            }
#pragma unroll
            for (int mi = 0; mi < 4; ++mi) {
#pragma unroll
                for (int ni = 0; ni < 4; ++ni) {
                    const uint32_t b0 = bS[ni >> 1][(ni & 1) * 2];
                    const uint32_t b1 = bS[ni >> 1][(ni & 1) * 2 + 1];
                    mma_f16(acc[mi][ni], aH[mi], b0, b1);
                    mma_f16(acc[mi][ni], aL[mi], b0, b1);
                }
            }
        }
    }

    const int er = lane >> 2;
    const int ec = (lane & 3) * 2;
#pragma unroll
    for (int mi = 0; mi < 4; ++mi) {
#pragma unroll
        for (int ni = 0; ni < 4; ++ni) {
            const int m = m0 + wm + mi * 16 + er;
            const int n = n0 + wn + ni * 8 + ec;
            const float* ac = acc[mi][ni];
            if (n < Nw) {
                const float b0 = bias[n], b1 = bias[n + 1];
                *(float2*)&C[(u64)m * ldc + n]       = make_float2(ac[0] + b0, ac[1] + b1);
                *(float2*)&C[(u64)(m + 8) * ldc + n] = make_float2(ac[2] + b0, ac[3] + b1);
            }
        }
    }
}

// ------------------------------------------------------------------
// fused flash attention (causal): per CTA 128 q-rows of one (b,h)
// warp w owns rows w*16..w*16+15, spans full 128-key chunk.
// smem: Qh/Ql [128][200], K [128][200], V [128][136] (rows = d)
// ------------------------------------------------------------------
#define QSTR 200
#define VSTR 136
#define FA_QBYTES (128*QSTR*2)            /* 51200 per term */
#define FA_KOFF   (2*FA_QBYTES)           /* 102400 */
#define FA_VOFF   (FA_KOFF + 128*QSTR*2)  /* 153600 */
#define FA_SMEM   (FA_VOFF + 128*VSTR*2)  /* 188416 */

__global__ void __launch_bounds__(256, 1)
k_fa()
{
    extern __shared__ h16 sm[];
    const uint32_t sb = smem_u32(sm);
    const int tid  = threadIdx.x;
    const int wid  = tid >> 5, lane = tid & 31;
    const int qt   = blockIdx.x;          // q tile 0..7
    const int z    = blockIdx.y;          // b*NH + h
    const int m0   = qt * 128;

    const h16* gQh = g_Qh_h + (u64)z * SS * QKD;
    const h16* gQl = g_Qh_l + (u64)z * SS * QKD;
    const h16* gK  = g_Kh   + (u64)z * SS * QKD;
    const h16* gV  = g_Vt   + (u64)z * VHD * SS;

    // prologue: Q (both terms) + K chunk 0, one commit group
    // QKD=192 halves = 24 cp16 per row -> 128*24 = 3072 cp16 per tensor
#pragma unroll
    for (int j = 0; j < 12; ++j) {
        const int i = tid + j * 256;          // 0..3071
        const int r = i / 24, c = i % 24;
        cp16(sb + (r * QSTR + c * 8) * 2,              gQh + ((u64)(m0 + r)) * QKD + c * 8);
        cp16(sb + FA_QBYTES + (r * QSTR + c * 8) * 2,  gQl + ((u64)(m0 + r)) * QKD + c * 8);
    }
#pragma unroll
    for (int j = 0; j < 12; ++j) {
        const int i = tid + j * 256;
        const int r = i / 24, c = i % 24;
        cp16(sb + FA_KOFF + (r * QSTR + c * 8) * 2, gK + (u64)r * QKD + c * 8);
    }
    cp_commit();

    const int a_row = lane & 15;
    const int a_kof = (lane >> 4) * 8;
    const int b_row = (lane & 7) + ((lane >> 4) & 1) * 8;
    const int b_kof = ((lane >> 3) & 1) * 8;
    const int er = lane >> 2;
    const int ec = (lane & 3) * 2;
    const int row0 = m0 + wid * 16 + er;
    const int row1 = row0 + 8;

    float o[16][4];
#pragma unroll
    for (int nb = 0; nb < 16; ++nb)
#pragma unroll
        for (int e = 0; e < 4; ++e) o[nb][e] = 0.f;
    float mr0 = -1e30f, mr1 = -1e30f, lr0 = 0.f, lr1 = 0.f;

    for (int j = 0; j <= qt; ++j) {
        // issue V_j: 128 d-rows x 128 keys = 2048 cp16
#pragma unroll
        for (int t = 0; t < 8; ++t) {
            const int i = tid + t * 256;      // 0..2047
            const int r = i >> 4, c = i & 15;
            cp16(sb + FA_VOFF + (r * VSTR + c * 8) * 2,
                 gV + (u64)r * SS + j * 128 + c * 8);
        }
        cp_commit();
        cp_wait<1>();            // K_j (and Q on j=0) arrived
        __syncthreads();

        // ---- QK: scores sc[16 n8][4]
        float sc[16][4];
#pragma unroll
        for (int nb = 0; nb < 16; ++nb)
#pragma unroll
            for (int e = 0; e < 4; ++e) sc[nb][e] = 0.f;

#pragma unroll
        for (int ks = 0; ks < 12; ++ks) {
            const int k0 = ks * 16;
            uint32_t aH[4], aL[4];
            const uint32_t ra = sb + ((wid * 16 + a_row) * QSTR + k0 + a_kof) * 2;
            ldm4(aH, ra);
            ldm4(aL, ra + FA_QBYTES);
#pragma unroll
            for (int g = 0; g < 8; ++g) {
                uint32_t bK[4];
                ldm4(bK, sb + FA_KOFF + ((g * 16 + b_row) * QSTR + k0 + b_kof) * 2);
                mma_f16(sc[2 * g],     aH, bK[0], bK[1]);
                mma_f16(sc[2 * g],     aL, bK[0], bK[1]);
                mma_f16(sc[2 * g + 1], aH, bK[2], bK[3]);
                mma_f16(sc[2 * g + 1], aL, bK[2], bK[3]);
            }
        }
        __syncthreads();          // all warps done reading K buffer

        // prefetch K_{j+1}
        if (j < qt) {
#pragma unroll
            for (int t = 0; t < 12; ++t) {
                const int i = tid + t * 256;
                const int r = i / 24, c = i % 24;
                cp16(sb + FA_KOFF + (r * QSTR + c * 8) * 2,
                     gK + ((u64)(j + 1) * 128 + r) * QKD + c * 8);
            }
            cp_commit();
        }

        // ---- scale + causal mask + online softmax
#pragma unroll
        for (int nb = 0; nb < 16; ++nb)
#pragma unroll
            for (int e = 0; e < 4; ++e) sc[nb][e] *= SCALE;
        if (j == qt) {
#pragma unroll
            for (int nb = 0; nb < 16; ++nb) {
                const int col = j * 128 + nb * 8 + ec;
                if (col     > row0) sc[nb][0] = -1e30f;
                if (col + 1 > row0) sc[nb][1] = -1e30f;
                if (col     > row1) sc[nb][2] = -1e30f;
                if (col + 1 > row1) sc[nb][3] = -1e30f;
            }
        }
        float mx0 = -1e30f, mx1 = -1e30f;
#pragma unroll
        for (int nb = 0; nb < 16; ++nb) {
            mx0 = fmaxf(mx0, fmaxf(sc[nb][0], sc[nb][1]));
            mx1 = fmaxf(mx1, fmaxf(sc[nb][2], sc[nb][3]));
        }
        mx0 = fmaxf(mx0, __shfl_xor_sync(0xFFFFFFFFu, mx0, 1));
        mx0 = fmaxf(mx0, __shfl_xor_sync(0xFFFFFFFFu, mx0, 2));
        mx1 = fmaxf(mx1, __shfl_xor_sync(0xFFFFFFFFu, mx1, 1));
        mx1 = fmaxf(mx1, __shfl_xor_sync(0xFFFFFFFFu, mx1, 2));
        const float mn0 = fmaxf(mr0, mx0), mn1 = fmaxf(mr1, mx1);
        const float al0 = __expf(mr0 - mn0), al1 = __expf(mr1 - mn1);
        mr0 = mn0; mr1 = mn1;
        float s0 = 0.f, s1 = 0.f;
#pragma unroll
        for (int nb = 0; nb < 16; ++nb) {
            sc[nb][0] = __expf(sc[nb][0] - mn0); s0 += sc[nb][0];
            sc[nb][1] = __expf(sc[nb][1] - mn0); s0 += sc[nb][1];
            sc[nb][2] = __expf(sc[nb][2] - mn1); s1 += sc[nb][2];
            sc[nb][3] = __expf(sc[nb][3] - mn1); s1 += sc[nb][3];
        }
        s0 += __shfl_xor_sync(0xFFFFFFFFu, s0, 1);
        s0 += __shfl_xor_sync(0xFFFFFFFFu, s0, 2);
        s1 += __shfl_xor_sync(0xFFFFFFFFu, s1, 1);
        s1 += __shfl_xor_sync(0xFFFFFFFFu, s1, 2);
        lr0 = lr0 * al0 + s0;
        lr1 = lr1 * al1 + s1;
#pragma unroll
        for (int nb = 0; nb < 16; ++nb) {
            o[nb][0] *= al0; o[nb][1] *= al0;
            o[nb][2] *= al1; o[nb][3] *= al1;
        }

        // ---- PV: A frags repacked from score accumulators
        if (j < qt) cp_wait<1>(); else cp_wait<0>();   // V_j arrived
        __syncthreads();
#pragma unroll
        for (int t = 0; t < 8; ++t) {
            uint32_t aP[4];
            aP[0] = pack2(sc[2 * t][0],     sc[2 * t][1]);
            aP[1] = pack2(sc[2 * t][2],     sc[2 * t][3]);
            aP[2] = pack2(sc[2 * t + 1][0], sc[2 * t + 1][1]);
            aP[3] = pack2(sc[2 * t + 1][2], sc[2 * t + 1][3]);
#pragma unroll
            for (int g = 0; g < 8; ++g) {
                uint32_t bV[4];
                ldm4(bV, sb + FA_VOFF + ((g * 16 + b_row) * VSTR + t * 16 + b_kof) * 2);
                mma_f16(o[2 * g],     aP, bV[0], bV[1]);
                mma_f16(o[2 * g + 1], aP, bV[2], bV[3]);
            }
        }
        __syncthreads();          // V buffer free for next chunk
    }

    // ---- epilogue: normalize + split-write to at_h/at_l
    const float i0 = 1.0f / lr0, i1 = 1.0f / lr1;
    const int b = z >> 4, h = z & 15;
#pragma unroll
    for (int nb = 0; nb < 16; ++nb) {
        const int d = nb * 8 + ec;
        const u64 r0o = (u64)(b * SS + row0) * (NH * VHD) + (u64)h * VHD + d;
        const u64 r1o = (u64)(b * SS + row1) * (NH * VHD) + (u64)h * VHD + d;
#pragma unroll
        for (int e = 0; e < 2; ++e) {
            float v0 = o[nb][e] * i0, v1 = o[nb][2 + e] * i1;
            h16 h0 = __float2half_rn(v0), h1 = __float2half_rn(v1);
            g_at_h[r0o + e] = h0; g_at_l[r0o + e] = __float2half_rn(v0 - __half2float(h0));
            g_at_h[r1o + e] = h1; g_at_l[r1o + e] = __float2half_rn(v1 - __half2float(h1));
        }
    }
}

// ------------------------------------------------------------------
// elementwise kernels
// ------------------------------------------------------------------
__global__ void k_split(const float* __restrict__ x, h16* __restrict__ h,
                        h16* __restrict__ l, int n)
{
    int i = blockIdx.x * 256 + threadIdx.x;
    if (i >= n) return;
    float v = x[i];
    h16 hv = __float2half_rn(v);
    h[i] = hv;
    l[i] = __float2half_rn(v - __half2float(hv));
}

__global__ void k_split1(const float* __restrict__ x, h16* __restrict__ o, int n)
{
    int i = blockIdx.x * 256 + threadIdx.x;
    if (i >= n) return;
    o[i] = __float2half_rn(x[i]);
}

__global__ void k_pack_wa(const float* __restrict__ wqa, const float* __restrict__ wkva)
{
    int c = blockIdx.x * 256 + threadIdx.x;
    int r = blockIdx.y;
    if (c >= HID) return;
    float v = 0.f;
    if (r < QL)        v = wqa[(u64)r * HID + c];
    else if (r < QKVW) v = wkva[(u64)(r - QL) * HID + c];
    g_wqkva[(u64)r * HID + c] = __float2half_rn(v);
}

__global__ void k_pack_bias(const float* __restrict__ bqa, const float* __restrict__ bkva)
{
    int i = blockIdx.x * 256 + threadIdx.x;
    if (i >= QKVN) return;
    float v = 0.f;
    if (i < QL)        v = bqa[i];
    else if (i < QKVW) v = bkva[i - QL];
    g_bqkva[i] = v;
}

__global__ void __launch_bounds__(256)
k_rmsnorm(const float* __restrict__ X, const float* __restrict__ w,
          h16* __restrict__ Yh, h16* __restrict__ Yl,
          int W, int inStride, int outStride)
{
    int row = blockIdx.x;
    const float* x = X + (u64)row * inStride;
    float s = 0.f;
    for (int i = threadIdx.x; i < W; i += 256) { float v = x[i]; s += v * v; }
    __shared__ float red[256];
    red[threadIdx.x] = s; __syncthreads();
    for (int off = 128; off > 0; off >>= 1) {
        if (threadIdx.x < off) red[threadIdx.x] += red[threadIdx.x + off];
        __syncthreads();
    }
    float r = rsqrtf(red[0] / (float)W + 1e-6f);
    h16* yh = Yh + (u64)row * outStride;
    h16* yl = Yl + (u64)row * outStride;
    for (int i = threadIdx.x; i < W; i += 256) {
        float v = w[i] * (x[i] * r);
        h16 hv = __float2half_rn(v);
        yh[i] = hv;
        yl[i] = __float2half_rn(v - __half2float(hv));
    }
}

__device__ __forceinline__ float rope_val(float x1, float x2, int s, int i, int odd)
{
    float inv = powf(10000.f, -(float)(2 * i) / (float)ROPEd);
    float sn, cs;
    sincosf((float)s * inv, &sn, &cs);
    return odd ? (x1 * sn + x2 * cs) : (x1 * cs - x2 * sn);
}
__device__ __forceinline__ void wr_split(h16* H, h16* L, u64 o, float v)
{
    h16 hv = __float2half_rn(v);
    H[o] = hv;
    L[o] = __float2half_rn(v - __half2float(hv));
}

__global__ void k_prep_q()
{
    int idx = blockIdx.x * blockDim.x + threadIdx.x;
    if (idx >= BB * SS * NH * QKD) return;
    int d = idx % QKD;
    int h = (idx / QKD) % NH;
    int s = (idx / (QKD * NH)) % SS;
    int b =  idx / (QKD * NH * SS);
    const float* qrow = g_q + (u64)(b * SS + s) * HID + h * QKD;
    float val;
    if (d < NOPEd) val = qrow[d];
    else {
        int i = (d - NOPEd) >> 1;
        val = rope_val(qrow[NOPEd + 2 * i], qrow[NOPEd + 2 * i + 1], s, i, (d - NOPEd) & 1);
    }
    wr_split(g_Qh_h, g_Qh_l, ((u64)(b * NH + h) * SS + s) * QKD + d, val);
}

__global__ void k_prep_k()
{
    int idx = blockIdx.x * blockDim.x + threadIdx.x;
    if (idx >= BB * SS * NH * QKD) return;
    int d = idx % QKD;
    int h = (idx / QKD) % NH;
    int s = (idx / (QKD * NH)) % SS;
    int b =  idx / (QKD * NH * SS);
    float val;
    if (d < NOPEd) {
        val = g_kvb[(u64)(b * SS + s) * (NH * KVOUT) + h * KVOUT + d];
    } else {
        int i = (d - NOPEd) >> 1;
        const float* kr = g_qkv + (u64)(b * SS + s) * QKVN + (QL + KVL);
        val = rope_val(kr[2 * i], kr[2 * i + 1], s, i, (d - NOPEd) & 1);
    }
    g_Kh[((u64)(b * NH + h) * SS + s) * QKD + d] = __float2half_rn(val);
}

__global__ void k_prep_v()
{
    int idx = blockIdx.x * blockDim.x + threadIdx.x;
    if (idx >= BB * NH * VHD * SS) return;
    int s = idx % SS;
    int d = (idx / SS) % VHD;
    int h = (idx / (SS * VHD)) % NH;
    int b =  idx / (SS * VHD * NH);
    float v = g_kvb[(u64)(b * SS + s) * (NH * KVOUT) + h * KVOUT + NOPEd + d];
    g_Vt[idx] = __float2half_rn(v);
}

// ------------------------------------------------------------------
// launch (two-stream fork/join, graph-capture-safe)
// ------------------------------------------------------------------
static inline void* sym(const void* s) { void* p; cudaGetSymbolAddress(&p, s); return p; }

extern "C" void kernel_launch(void* const* d_in, const int* in_sizes, int n_in,
                              void* d_out, int out_size)
{
    const float* hs        = (const float*)d_in[0];
    const float* wq_a_w    = (const float*)d_in[2];
    const float* wq_a_b    = (const float*)d_in[3];
    const float* q_norm_w  = (const float*)d_in[4];
    const float* wq_b_w    = (const float*)d_in[5];
    const float* wq_b_b    = (const float*)d_in[6];
    const float* wkv_a_w   = (const float*)d_in[7];
    const float* wkv_a_b   = (const float*)d_in[8];
    const float* kv_norm_w = (const float*)d_in[9];
    const float* wkv_b_w   = (const float*)d_in[10];
    const float* wkv_b_b   = (const float*)d_in[11];
    const float* wo_w      = (const float*)d_in[12];
    const float* wo_b      = (const float*)d_in[13];
    float* out = (float*)d_out;

    static bool init = false;
    static cudaStream_t s1;
    static cudaEvent_t e0, e_wqb, e_g13, e_kv;
    if (!init) {
        cudaFuncSetAttribute(k_mma, cudaFuncAttributeMaxDynamicSharedMemorySize, SMEM_BYTES);
        cudaFuncSetAttribute(k_fa,  cudaFuncAttributeMaxDynamicSharedMemorySize, FA_SMEM);
        cudaStreamCreateWithFlags(&s1, cudaStreamNonBlocking);
        cudaEventCreateWithFlags(&e0,    cudaEventDisableTiming);
        cudaEventCreateWithFlags(&e_wqb, cudaEventDisableTiming);
        cudaEventCreateWithFlags(&e_g13, cudaEventDisableTiming);
        cudaEventCreateWithFlags(&e_kv,  cudaEventDisableTiming);
        init = true;
    }

    h16 *hs_h=(h16*)sym(g_hs_h), *hs_l=(h16*)sym(g_hs_l);
    h16 *wqkva=(h16*)sym(g_wqkva);
    float *bqkva=(float*)sym(g_bqkva);
    h16 *wqb=(h16*)sym(g_wqb), *wkvb=(h16*)sym(g_wkvb), *wo=(h16*)sym(g_wo);
    float *qkv=(float*)sym(g_qkv), *q=(float*)sym(g_q), *kvb=(float*)sym(g_kvb);
    h16 *qln_h=(h16*)sym(g_qln_h), *qln_l=(h16*)sym(g_qln_l);
    h16 *kvln_h=(h16*)sym(g_kvln_h), *kvln_l=(h16*)sym(g_kvln_l);
    h16 *at_h=(h16*)sym(g_at_h), *at_l=(h16*)sym(g_at_l);

    // fork: side stream does the weight splits for later GEMMs
    cudaEventRecord(e0, 0);
    cudaStreamWaitEvent(s1, e0, 0);
    k_split1<<<(HID*QL + 255)/256, 256, 0, s1>>>(wq_b_w, wqb, HID*QL);
    cudaEventRecord(e_wqb, s1);
    k_split1<<<(NH*KVOUT*KVL + 255)/256, 256, 0, s1>>>(wkv_b_w, wkvb, NH*KVOUT*KVL);
    k_split1<<<(HID*NH*VHD + 255)/256, 256, 0, s1>>>(wo_w, wo, HID*NH*VHD);

    // main stream: inputs for merged first GEMM
    k_split<<<(NT*HID + 255)/256, 256>>>(hs, hs_h, hs_l, NT*HID);
    k_pack_wa<<<dim3((HID + 255)/256, QKVN), 256>>>(wq_a_w, wkv_a_w);
    k_pack_bias<<<(QKVN + 255)/256, 256>>>(wq_a_b, wkv_a_b);

    // merged q_lat + kv_lat + k_rope projection
    k_mma<<<dim3(QKVN/128, NT/128), 256, SMEM_BYTES>>>(
        hs_h, hs_l, wqkva, qkv, bqkva, NT, QKVN, HID, QKVW, QKVN);
    cudaEventRecord(e_g13, 0);

    // kv chain on side stream
    cudaStreamWaitEvent(s1, e_g13, 0);
    k_rmsnorm<<<NT, 256, 0, s1>>>(qkv + QL, kv_norm_w, kvln_h, kvln_l, KVL, QKVN, KVL);
    k_mma<<<dim3(NH*KVOUT/128, NT/128), 256, SMEM_BYTES, s1>>>(
        kvln_h, kvln_l, wkvb, kvb, wkv_b_b, NT, NH*KVOUT, KVL, NH*KVOUT, NH*KVOUT);
    k_prep_k<<<(BB*SS*NH*QKD + 255)/256, 256, 0, s1>>>();
    k_prep_v<<<(BB*NH*VHD*SS + 255)/256, 256, 0, s1>>>();
    cudaEventRecord(e_kv, s1);

    // q chain on main stream
    k_rmsnorm<<<NT, 256>>>(qkv, q_norm_w, qln_h, qln_l, QL, QKVN, QL);
    cudaStreamWaitEvent(0, e_wqb, 0);
    k_mma<<<dim3(HID/128, NT/128), 256, SMEM_BYTES>>>(
        qln_h, qln_l, wqb, q, wq_b_b, NT, HID, QL, HID, HID);
    k_prep_q<<<(BB*SS*NH*QKD + 255)/256, 256>>>();

    // join kv chain, then fused flash attention
    cudaStreamWaitEvent(0, e_kv, 0);
    k_fa<<<dim3(SS/128, BB*NH), 256, FA_SMEM>>>();

    // output projection
    k_mma<<<dim3(HID/128, NT/128), 256, SMEM_BYTES>>>(
        at_h, at_l, wo, out, wo_b, NT, HID, NH*VHD, HID, HID);
}

// round 13
// speedup vs baseline: 1.4355x; 1.0250x over previous
#include <cuda_runtime.h>
#include <cuda_fp16.h>
#include <math.h>
#include <stdint.h>

typedef unsigned long long u64;
typedef __half h16;

#define BB 2
#define SS 1024
#define HID 3072
#define NH 16
#define QL 1536
#define KVL 512
#define NOPEd 128
#define ROPEd 64
#define QKD 192
#define VHD 128
#define NT (BB*SS)
#define KVOUT 256
#define QKVN 2176
#define QKVW 2112
#define SCALE 0.07216878364870323f

// ------------------------------------------------------------------
// scratch (device globals)
// ------------------------------------------------------------------
#define AL __align__(256)
__device__ AL h16   g_hs_h [NT*HID],      g_hs_l [NT*HID];
__device__ AL h16   g_wqkva[QKVN*HID];
__device__ AL float g_bqkva[QKVN];
__device__ AL h16   g_wqb [HID*QL];
__device__ AL h16   g_wkvb[NH*KVOUT*KVL];
__device__ AL h16   g_wo  [HID*NH*VHD];
__device__ AL float g_qkv [NT*QKVN];
__device__ AL h16   g_qln_h[NT*QL],       g_qln_l[NT*QL];
__device__ AL h16   g_kvln_h[NT*KVL],     g_kvln_l[NT*KVL];
__device__ AL h16   g_Qh_h[(u64)BB*NH*SS*QKD], g_Qh_l[(u64)BB*NH*SS*QKD];
__device__ AL h16   g_Kh  [(u64)BB*NH*SS*QKD];
__device__ AL h16   g_Vt  [(u64)BB*NH*VHD*SS];    /* [b][h][d][t] */
__device__ AL h16   g_at_h[NT*NH*VHD],    g_at_l[NT*NH*VHD];

// ------------------------------------------------------------------
// PTX helpers
// ------------------------------------------------------------------
__device__ __forceinline__ uint32_t smem_u32(const void* p) {
    uint32_t a;
    asm("{ .reg .u64 t; cvta.to.shared.u64 t, %1; cvt.u32.u64 %0, t; }" : "=r"(a) : "l"(p));
    return a;
}
__device__ __forceinline__ void cp16(uint32_t dst, const void* src) {
    asm volatile("cp.async.cg.shared.global [%0], [%1], 16;" :: "r"(dst), "l"(src));
}
__device__ __forceinline__ void cp_commit() {
    asm volatile("cp.async.commit_group;" ::: "memory");
}
template<int N> __device__ __forceinline__ void cp_wait() {
    asm volatile("cp.async.wait_group %0;" :: "n"(N) : "memory");
}
__device__ __forceinline__ void ldm4(uint32_t* r, uint32_t addr) {
    asm volatile("ldmatrix.sync.aligned.m8n8.x4.shared.b16 {%0,%1,%2,%3}, [%4];"
        : "=r"(r[0]), "=r"(r[1]), "=r"(r[2]), "=r"(r[3]) : "r"(addr));
}
__device__ __forceinline__ void mma_f16(float* c, const uint32_t* a, uint32_t b0, uint32_t b1) {
    asm volatile(
        "mma.sync.aligned.m16n8k16.row.col.f32.f16.f16.f32 "
        "{%0,%1,%2,%3}, {%4,%5,%6,%7}, {%8,%9}, {%0,%1,%2,%3};"
        : "+f"(c[0]), "+f"(c[1]), "+f"(c[2]), "+f"(c[3])
        : "r"(a[0]), "r"(a[1]), "r"(a[2]), "r"(a[3]), "r"(b0), "r"(b1));
}
__device__ __forceinline__ uint32_t pack2(float x, float y) {
    __half2 h = __floats2half2_rn(x, y);
    return *(uint32_t*)&h;
}
__device__ __forceinline__ void wr_split(h16* H, h16* L, u64 o, float v)
{
    h16 hv = __float2half_rn(v);
    H[o] = hv;
    L[o] = __float2half_rn(v - __half2float(hv));
}

// ------------------------------------------------------------------
// fp16 2-term split GEMM: C = (Ah+Al) @ B^T + bias
// mode 0: float out (stride ldc, store-guard n<Nw)
// mode 1: Q head-gather + RoPE -> g_Qh_h/g_Qh_l     (N = 3072)
// mode 2: KV head-gather -> g_Kh (nope) / g_Vt (v)   (N = 4096)
// ------------------------------------------------------------------
#define LDSX 40
#define TSZ  (128*LDSX)
#define STGB (3*TSZ*2)
#define NSTG 4
#define SMEM_BYTES (NSTG*STGB)

__global__ void __launch_bounds__(256, 1)
k_mma(const h16* __restrict__ Ah, const h16* __restrict__ Al,
      const h16* __restrict__ B,
      float* __restrict__ C, const float* __restrict__ bias,
      int M, int N, int K, int Nw, int ldc, int mode)
{
    extern __shared__ h16 sm[];
    const uint32_t sb = smem_u32(sm);
    const int tid  = threadIdx.x;
    const int wid  = tid >> 5, lane = tid & 31;
    const int wm   = (wid & 1) * 64;
    const int wn   = (wid >> 1) * 32;
    const int m0   = blockIdx.y * 128, n0 = blockIdx.x * 128;

    const u64 aoff0 = (u64)m0 * K;
    const u64 boff0 = (u64)n0 * K;
    const int NC = K >> 5;

    auto fill = [&](int stage, int c) {
        const uint32_t sbase = sb + stage * STGB;
        const u64 ka = aoff0 + c * 32;
        const u64 kb = boff0 + c * 32;
#pragma unroll
        for (int j = 0; j < 6; ++j) {
            const int i   = tid + j * 256;
            const int t   = i >> 9;
            const int row = (i >> 2) & 127;
            const int ch  = i & 3;
            const h16* g  = (t == 0) ? Ah : (t == 1) ? Al : B;
            const u64 base = (t < 2) ? ka : kb;
            const uint32_t dst = sbase + (t * TSZ + row * LDSX + ch * 8) * 2;
            cp16(dst, g + base + (u64)row * K + ch * 8);
        }
    };

    float acc[4][4][4];
#pragma unroll
    for (int a = 0; a < 4; ++a)
#pragma unroll
        for (int b = 0; b < 4; ++b)
#pragma unroll
            for (int d = 0; d < 4; ++d) acc[a][b][d] = 0.f;

#pragma unroll
    for (int p = 0; p < NSTG - 1; ++p) { if (p < NC) fill(p, p); cp_commit(); }

    const int a_row = lane & 15;
    const int a_kof = (lane >> 4) * 8;
    const int b_row = (lane & 7) + ((lane >> 4) & 1) * 8;
    const int b_kof = ((lane >> 3) & 1) * 8;

    for (int c = 0; c < NC; ++c) {
        cp_wait<NSTG - 2>();
        __syncthreads();
        if (c + NSTG - 1 < NC) fill((c + NSTG - 1) & (NSTG - 1), c + NSTG - 1);
        cp_commit();

        const uint32_t st = sb + (c & (NSTG - 1)) * STGB;
#pragma unroll
        for (int ks = 0; ks < 2; ++ks) {
            const int k0s = ks * 16;
            uint32_t aH[4][4], aL[4][4], bS[2][4];
#pragma unroll
            for (int mi = 0; mi < 4; ++mi) {
                const uint32_t ra = st + ((wm + mi * 16 + a_row) * LDSX + k0s + a_kof) * 2;
                ldm4(aH[mi], ra);
                ldm4(aL[mi], ra + TSZ * 2);
            }
#pragma unroll
            for (int np = 0; np < 2; ++np) {
                const uint32_t rb = st + (2 * TSZ + (wn + np * 16 + b_row) * LDSX + k0s + b_kof) * 2;
                ldm4(bS[np], rb);
            }
#pragma unroll
            for (int mi = 0; mi < 4; ++mi) {
#pragma unroll
                for (int ni = 0; ni < 4; ++ni) {
                    const uint32_t b0 = bS[ni >> 1][(ni & 1) * 2];
                    const uint32_t b1 = bS[ni >> 1][(ni & 1) * 2 + 1];
                    mma_f16(acc[mi][ni], aH[mi], b0, b1);
                    mma_f16(acc[mi][ni], aL[mi], b0, b1);
                }
            }
        }
    }

    const int er = lane >> 2;
    const int ec = (lane & 3) * 2;
#pragma unroll
    for (int mi = 0; mi < 4; ++mi) {
#pragma unroll
        for (int ni = 0; ni < 4; ++ni) {
            const int mrow = m0 + wm + mi * 16 + er;
            const int n = n0 + wn + ni * 8 + ec;
            const float* ac = acc[mi][ni];
            if (mode == 0) {
                if (n < Nw) {
                    const float b0 = bias[n], b1 = bias[n + 1];
                    *(float2*)&C[(u64)mrow * ldc + n]       = make_float2(ac[0] + b0, ac[1] + b1);
                    *(float2*)&C[(u64)(mrow + 8) * ldc + n] = make_float2(ac[2] + b0, ac[3] + b1);
                }
            } else if (mode == 1) {
                // Q: n = h*192 + d; rope pair (d, d+1) for d>=128
                const int h = n / QKD, d = n - h * QKD;
#pragma unroll
                for (int r = 0; r < 2; ++r) {
                    const int m = mrow + r * 8;
                    const int b = m >> 10, s = m & (SS - 1);
                    float v0 = ac[2 * r]     + bias[n];
                    float v1 = ac[2 * r + 1] + bias[n + 1];
                    if (d >= NOPEd) {
                        const int i = (d - NOPEd) >> 1;
                        float inv = powf(10000.f, -(float)(2 * i) / (float)ROPEd);
                        float sn, cs; sincosf((float)s * inv, &sn, &cs);
                        float r1 = v0 * cs - v1 * sn;
                        float r2 = v0 * sn + v1 * cs;
                        v0 = r1; v1 = r2;
                    }
                    const u64 o = ((u64)(b * NH + h) * SS + s) * QKD + d;
                    wr_split(g_Qh_h, g_Qh_l, o,     v0);
                    wr_split(g_Qh_h, g_Qh_l, o + 1, v1);
                }
            } else {
                // KV: n = h*256 + c; c<128 -> K_nope, else -> V (transposed)
                const int h = n >> 8, cc = n & 255;
#pragma unroll
                for (int r = 0; r < 2; ++r) {
                    const int m = mrow + r * 8;
                    const int b = m >> 10, s = m & (SS - 1);
                    const float v0 = ac[2 * r]     + bias[n];
                    const float v1 = ac[2 * r + 1] + bias[n + 1];
                    if (cc < NOPEd) {
                        const u64 o = ((u64)(b * NH + h) * SS + s) * QKD + cc;
                        g_Kh[o]     = __float2half_rn(v0);
                        g_Kh[o + 1] = __float2half_rn(v1);
                    } else {
                        const int d = cc - NOPEd;
                        const u64 o = ((u64)(b * NH + h) * VHD + d) * SS + s;
                        g_Vt[o]      = __float2half_rn(v0);
                        g_Vt[o + SS] = __float2half_rn(v1);
                    }
                }
            }
        }
    }
}

// ------------------------------------------------------------------
// fused flash attention (causal): per CTA 128 q-rows of one (b,h)
// ------------------------------------------------------------------
#define QSTR 200
#define VSTR 136
#define FA_QBYTES (128*QSTR*2)
#define FA_KOFF   (2*FA_QBYTES)
#define FA_VOFF   (FA_KOFF + 128*QSTR*2)
#define FA_SMEM   (FA_VOFF + 128*VSTR*2)  /* 188416 */

__global__ void __launch_bounds__(256, 1)
k_fa()
{
    extern __shared__ h16 sm[];
    const uint32_t sb = smem_u32(sm);
    const int tid  = threadIdx.x;
    const int wid  = tid >> 5, lane = tid & 31;
    const int qt   = (int)(gridDim.x - 1 - blockIdx.x);   // heavy tiles first
    const int z    = blockIdx.y;
    const int m0   = qt * 128;

    const h16* gQh = g_Qh_h + (u64)z * SS * QKD;
    const h16* gQl = g_Qh_l + (u64)z * SS * QKD;
    const h16* gK  = g_Kh   + (u64)z * SS * QKD;
    const h16* gV  = g_Vt   + (u64)z * VHD * SS;

    // prologue: Q (both terms) + K chunk 0
#pragma unroll
    for (int j = 0; j < 12; ++j) {
        const int i = tid + j * 256;
        const int r = i / 24, c = i % 24;
        cp16(sb + (r * QSTR + c * 8) * 2,              gQh + ((u64)(m0 + r)) * QKD + c * 8);
        cp16(sb + FA_QBYTES + (r * QSTR + c * 8) * 2,  gQl + ((u64)(m0 + r)) * QKD + c * 8);
    }
#pragma unroll
    for (int j = 0; j < 12; ++j) {
        const int i = tid + j * 256;
        const int r = i / 24, c = i % 24;
        cp16(sb + FA_KOFF + (r * QSTR + c * 8) * 2, gK + (u64)r * QKD + c * 8);
    }
    cp_commit();

    const int a_row = lane & 15;
    const int a_kof = (lane >> 4) * 8;
    const int b_row = (lane & 7) + ((lane >> 4) & 1) * 8;
    const int b_kof = ((lane >> 3) & 1) * 8;
    const int er = lane >> 2;
    const int ec = (lane & 3) * 2;
    const int row0 = m0 + wid * 16 + er;
    const int row1 = row0 + 8;

    float o[16][4];
#pragma unroll
    for (int nb = 0; nb < 16; ++nb)
#pragma unroll
        for (int e = 0; e < 4; ++e) o[nb][e] = 0.f;
    float mr0 = -1e30f, mr1 = -1e30f, lr0 = 0.f, lr1 = 0.f;

    for (int j = 0; j <= qt; ++j) {
        // issue V_j
#pragma unroll
        for (int t = 0; t < 8; ++t) {
            const int i = tid + t * 256;
            const int r = i >> 4, c = i & 15;
            cp16(sb + FA_VOFF + (r * VSTR + c * 8) * 2,
                 gV + (u64)r * SS + j * 128 + c * 8);
        }
        cp_commit();
        cp_wait<1>();
        __syncthreads();

        float sc[16][4];
#pragma unroll
        for (int nb = 0; nb < 16; ++nb)
#pragma unroll
            for (int e = 0; e < 4; ++e) sc[nb][e] = 0.f;

#pragma unroll
        for (int ks = 0; ks < 12; ++ks) {
            const int k0 = ks * 16;
            uint32_t aH[4], aL[4];
            const uint32_t ra = sb + ((wid * 16 + a_row) * QSTR + k0 + a_kof) * 2;
            ldm4(aH, ra);
            ldm4(aL, ra + FA_QBYTES);
#pragma unroll
            for (int g = 0; g < 8; ++g) {
                uint32_t bK[4];
                ldm4(bK, sb + FA_KOFF + ((g * 16 + b_row) * QSTR + k0 + b_kof) * 2);
                mma_f16(sc[2 * g],     aH, bK[0], bK[1]);
                mma_f16(sc[2 * g],     aL, bK[0], bK[1]);
                mma_f16(sc[2 * g + 1], aH, bK[2], bK[3]);
                mma_f16(sc[2 * g + 1], aL, bK[2], bK[3]);
            }
        }
        __syncthreads();

        if (j < qt) {
#pragma unroll
            for (int t = 0; t < 12; ++t) {
                const int i = tid + t * 256;
                const int r = i / 24, c = i % 24;
                cp16(sb + FA_KOFF + (r * QSTR + c * 8) * 2,
                     gK + ((u64)(j + 1) * 128 + r) * QKD + c * 8);
            }
            cp_commit();
        }

#pragma unroll
        for (int nb = 0; nb < 16; ++nb)
#pragma unroll
            for (int e = 0; e < 4; ++e) sc[nb][e] *= SCALE;
        if (j == qt) {
#pragma unroll
            for (int nb = 0; nb < 16; ++nb) {
                const int col = j * 128 + nb * 8 + ec;
                if (col     > row0) sc[nb][0] = -1e30f;
                if (col + 1 > row0) sc[nb][1] = -1e30f;
                if (col     > row1) sc[nb][2] = -1e30f;
                if (col + 1 > row1) sc[nb][3] = -1e30f;
            }
        }
        float mx0 = -1e30f, mx1 = -1e30f;
#pragma unroll
        for (int nb = 0; nb < 16; ++nb) {
            mx0 = fmaxf(mx0, fmaxf(sc[nb][0], sc[nb][1]));
            mx1 = fmaxf(mx1, fmaxf(sc[nb][2], sc[nb][3]));
        }
        mx0 = fmaxf(mx0, __shfl_xor_sync(0xFFFFFFFFu, mx0, 1));
        mx0 = fmaxf(mx0, __shfl_xor_sync(0xFFFFFFFFu, mx0, 2));
        mx1 = fmaxf(mx1, __shfl_xor_sync(0xFFFFFFFFu, mx1, 1));
        mx1 = fmaxf(mx1, __shfl_xor_sync(0xFFFFFFFFu, mx1, 2));
        const float mn0 = fmaxf(mr0, mx0), mn1 = fmaxf(mr1, mx1);
        const float al0 = __expf(mr0 - mn0), al1 = __expf(mr1 - mn1);
        mr0 = mn0; mr1 = mn1;
        float s0 = 0.f, s1 = 0.f;
#pragma unroll
        for (int nb = 0; nb < 16; ++nb) {
            sc[nb][0] = __expf(sc[nb][0] - mn0); s0 += sc[nb][0];
            sc[nb][1] = __expf(sc[nb][1] - mn0); s0 += sc[nb][1];
            sc[nb][2] = __expf(sc[nb][2] - mn1); s1 += sc[nb][2];
            sc[nb][3] = __expf(sc[nb][3] - mn1); s1 += sc[nb][3];
        }
        s0 += __shfl_xor_sync(0xFFFFFFFFu, s0, 1);
        s0 += __shfl_xor_sync(0xFFFFFFFFu, s0, 2);
        s1 += __shfl_xor_sync(0xFFFFFFFFu, s1, 1);
        s1 += __shfl_xor_sync(0xFFFFFFFFu, s1, 2);
        lr0 = lr0 * al0 + s0;
        lr1 = lr1 * al1 + s1;
#pragma unroll
        for (int nb = 0; nb < 16; ++nb) {
            o[nb][0] *= al0; o[nb][1] *= al0;
            o[nb][2] *= al1; o[nb][3] *= al1;
        }

        if (j < qt) cp_wait<1>(); else cp_wait<0>();
        __syncthreads();
#pragma unroll
        for (int t = 0; t < 8; ++t) {
            uint32_t aP[4];
            aP[0] = pack2(sc[2 * t][0],     sc[2 * t][1]);
            aP[1] = pack2(sc[2 * t][2],     sc[2 * t][3]);
            aP[2] = pack2(sc[2 * t + 1][0], sc[2 * t + 1][1]);
            aP[3] = pack2(sc[2 * t + 1][2], sc[2 * t + 1][3]);
#pragma unroll
            for (int g = 0; g < 8; ++g) {
                uint32_t bV[4];
                ldm4(bV, sb + FA_VOFF + ((g * 16 + b_row) * VSTR + t * 16 + b_kof) * 2);
                mma_f16(o[2 * g],     aP, bV[0], bV[1]);
                mma_f16(o[2 * g + 1], aP, bV[2], bV[3]);
            }
        }
        __syncthreads();
    }

    const float i0 = 1.0f / lr0, i1 = 1.0f / lr1;
    const int b = z >> 4, h = z & 15;
#pragma unroll
    for (int nb = 0; nb < 16; ++nb) {
        const int d = nb * 8 + ec;
        const u64 r0o = (u64)(b * SS + row0) * (NH * VHD) + (u64)h * VHD + d;
        const u64 r1o = (u64)(b * SS + row1) * (NH * VHD) + (u64)h * VHD + d;
#pragma unroll
        for (int e = 0; e < 2; ++e) {
            float v0 = o[nb][e] * i0, v1 = o[nb][2 + e] * i1;
            h16 h0 = __float2half_rn(v0), h1 = __float2half_rn(v1);
            g_at_h[r0o + e] = h0; g_at_l[r0o + e] = __float2half_rn(v0 - __half2float(h0));
            g_at_h[r1o + e] = h1; g_at_l[r1o + e] = __float2half_rn(v1 - __half2float(h1));
        }
    }
}

// ------------------------------------------------------------------
// elementwise kernels
// ------------------------------------------------------------------
__global__ void k_split(const float* __restrict__ x, h16* __restrict__ h,
                        h16* __restrict__ l, int n)
{
    int i = blockIdx.x * 256 + threadIdx.x;
    if (i >= n) return;
    float v = x[i];
    h16 hv = __float2half_rn(v);
    h[i] = hv;
    l[i] = __float2half_rn(v - __half2float(hv));
}

__global__ void k_split1(const float* __restrict__ x, h16* __restrict__ o, int n)
{
    int i = blockIdx.x * 256 + threadIdx.x;
    if (i >= n) return;
    o[i] = __float2half_rn(x[i]);
}

__global__ void k_pack_wa(const float* __restrict__ wqa, const float* __restrict__ wkva)
{
    int c = blockIdx.x * 256 + threadIdx.x;
    int r = blockIdx.y;
    if (c >= HID) return;
    float v = 0.f;
    if (r < QL)        v = wqa[(u64)r * HID + c];
    else if (r < QKVW) v = wkva[(u64)(r - QL) * HID + c];
    g_wqkva[(u64)r * HID + c] = __float2half_rn(v);
}

__global__ void k_pack_bias(const float* __restrict__ bqa, const float* __restrict__ bkva)
{
    int i = blockIdx.x * 256 + threadIdx.x;
    if (i >= QKVN) return;
    float v = 0.f;
    if (i < QL)        v = bqa[i];
    else if (i < QKVW) v = bkva[i - QL];
    g_bqkva[i] = v;
}

__global__ void __launch_bounds__(256)
k_rmsnorm(const float* __restrict__ X, const float* __restrict__ w,
          h16* __restrict__ Yh, h16* __restrict__ Yl,
          int W, int inStride, int outStride)
{
    int row = blockIdx.x;
    const float* x = X + (u64)row * inStride;
    float s = 0.f;
    for (int i = threadIdx.x; i < W; i += 256) { float v = x[i]; s += v * v; }
    __shared__ float red[256];
    red[threadIdx.x] = s; __syncthreads();
    for (int off = 128; off > 0; off >>= 1) {
        if (threadIdx.x < off) red[threadIdx.x] += red[threadIdx.x + off];
        __syncthreads();
    }
    float r = rsqrtf(red[0] / (float)W + 1e-6f);
    h16* yh = Yh + (u64)row * outStride;
    h16* yl = Yl + (u64)row * outStride;
    for (int i = threadIdx.x; i < W; i += 256) {
        float v = w[i] * (x[i] * r);
        h16 hv = __float2half_rn(v);
        yh[i] = hv;
        yl[i] = __float2half_rn(v - __half2float(hv));
    }
}

// K rope columns (128..191) for all heads, from g_qkv's k_rope slice
__global__ void k_prep_krope()
{
    int idx = blockIdx.x * 256 + threadIdx.x;
    if (idx >= BB * SS * (ROPEd / 2)) return;
    int i = idx & 31;
    int s = (idx >> 5) & (SS - 1);
    int b = idx >> 15;
    const float* kr = g_qkv + (u64)(b * SS + s) * QKVN + (QL + KVL);
    float x1 = kr[2 * i], x2 = kr[2 * i + 1];
    float inv = powf(10000.f, -(float)(2 * i) / (float)ROPEd);
    float sn, cs; sincosf((float)s * inv, &sn, &cs);
    h16 r1 = __float2half_rn(x1 * cs - x2 * sn);
    h16 r2 = __float2half_rn(x1 * sn + x2 * cs);
#pragma unroll
    for (int h = 0; h < NH; ++h) {
        u64 o = ((u64)(b * NH + h) * SS + s) * QKD + NOPEd + 2 * i;
        g_Kh[o] = r1; g_Kh[o + 1] = r2;
    }
}

// ------------------------------------------------------------------
// launch (two-stream fork/join, graph-capture-safe)
// ------------------------------------------------------------------
static inline void* sym(const void* s) { void* p; cudaGetSymbolAddress(&p, s); return p; }

extern "C" void kernel_launch(void* const* d_in, const int* in_sizes, int n_in,
                              void* d_out, int out_size)
{
    const float* hs        = (const float*)d_in[0];
    const float* wq_a_w    = (const float*)d_in[2];
    const float* wq_a_b    = (const float*)d_in[3];
    const float* q_norm_w  = (const float*)d_in[4];
    const float* wq_b_w    = (const float*)d_in[5];
    const float* wq_b_b    = (const float*)d_in[6];
    const float* wkv_a_w   = (const float*)d_in[7];
    const float* wkv_a_b   = (const float*)d_in[8];
    const float* kv_norm_w = (const float*)d_in[9];
    const float* wkv_b_w   = (const float*)d_in[10];
    const float* wkv_b_b   = (const float*)d_in[11];
    const float* wo_w      = (const float*)d_in[12];
    const float* wo_b      = (const float*)d_in[13];
    float* out = (float*)d_out;

    static bool init = false;
    static cudaStream_t s1;
    static cudaEvent_t e0, e_wqb, e_g13, e_kv;
    if (!init) {
        cudaFuncSetAttribute(k_mma, cudaFuncAttributeMaxDynamicSharedMemorySize, SMEM_BYTES);
        cudaFuncSetAttribute(k_fa,  cudaFuncAttributeMaxDynamicSharedMemorySize, FA_SMEM);
        cudaStreamCreateWithFlags(&s1, cudaStreamNonBlocking);
        cudaEventCreateWithFlags(&e0,    cudaEventDisableTiming);
        cudaEventCreateWithFlags(&e_wqb, cudaEventDisableTiming);
        cudaEventCreateWithFlags(&e_g13, cudaEventDisableTiming);
        cudaEventCreateWithFlags(&e_kv,  cudaEventDisableTiming);
        init = true;
    }

    h16 *hs_h=(h16*)sym(g_hs_h), *hs_l=(h16*)sym(g_hs_l);
    h16 *wqkva=(h16*)sym(g_wqkva);
    float *bqkva=(float*)sym(g_bqkva);
    h16 *wqb=(h16*)sym(g_wqb), *wkvb=(h16*)sym(g_wkvb), *wo=(h16*)sym(g_wo);
    float *qkv=(float*)sym(g_qkv);
    h16 *qln_h=(h16*)sym(g_qln_h), *qln_l=(h16*)sym(g_qln_l);
    h16 *kvln_h=(h16*)sym(g_kvln_h), *kvln_l=(h16*)sym(g_kvln_l);
    h16 *at_h=(h16*)sym(g_at_h), *at_l=(h16*)sym(g_at_l);

    // fork: side stream does the weight splits for later GEMMs
    cudaEventRecord(e0, 0);
    cudaStreamWaitEvent(s1, e0, 0);
    k_split1<<<(HID*QL + 255)/256, 256, 0, s1>>>(wq_b_w, wqb, HID*QL);
    cudaEventRecord(e_wqb, s1);
    k_split1<<<(NH*KVOUT*KVL + 255)/256, 256, 0, s1>>>(wkv_b_w, wkvb, NH*KVOUT*KVL);
    k_split1<<<(HID*NH*VHD + 255)/256, 256, 0, s1>>>(wo_w, wo, HID*NH*VHD);

    // main stream: inputs for merged first GEMM
    k_split<<<(NT*HID + 255)/256, 256>>>(hs, hs_h, hs_l, NT*HID);
    k_pack_wa<<<dim3((HID + 255)/256, QKVN), 256>>>(wq_a_w, wkv_a_w);
    k_pack_bias<<<(QKVN + 255)/256, 256>>>(wq_a_b, wkv_a_b);

    // merged q_lat + kv_lat + k_rope projection
    k_mma<<<dim3(QKVN/128, NT/128), 256, SMEM_BYTES>>>(
        hs_h, hs_l, wqkva, qkv, bqkva, NT, QKVN, HID, QKVW, QKVN, 0);
    cudaEventRecord(e_g13, 0);

    // kv chain on side stream: krope + rmsnorm + fused wkv_b GEMM (writes Kh/Vt)
    cudaStreamWaitEvent(s1, e_g13, 0);
    k_prep_krope<<<(BB*SS*(ROPEd/2) + 255)/256, 256, 0, s1>>>();
    k_rmsnorm<<<NT, 256, 0, s1>>>(qkv + QL, kv_norm_w, kvln_h, kvln_l, KVL, QKVN, KVL);
    k_mma<<<dim3(NH*KVOUT/128, NT/128), 256, SMEM_BYTES, s1>>>(
        kvln_h, kvln_l, wkvb, nullptr, wkv_b_b, NT, NH*KVOUT, KVL, NH*KVOUT, NH*KVOUT, 2);
    cudaEventRecord(e_kv, s1);

    // q chain on main stream: rmsnorm + fused wq_b GEMM (writes Qh split + rope)
    k_rmsnorm<<<NT, 256>>>(qkv, q_norm_w, qln_h, qln_l, QL, QKVN, QL);
    cudaStreamWaitEvent(0, e_wqb, 0);
    k_mma<<<dim3(HID/128, NT/128), 256, SMEM_BYTES>>>(
        qln_h, qln_l, wqb, nullptr, wq_b_b, NT, HID, QL, HID, HID, 1);

    // join kv chain, then fused flash attention
    cudaStreamWaitEvent(0, e_kv, 0);
    k_fa<<<dim3(SS/128, BB*NH), 256, FA_SMEM>>>();

    // output projection
    k_mma<<<dim3(HID/128, NT/128), 256, SMEM_BYTES>>>(
        at_h, at_l, wo, out, wo_b, NT, HID, NH*VHD, HID, HID, 0);
}

// round 14
// speedup vs baseline: 2.1949x; 1.5290x over previous
#include <cuda_runtime.h>
#include <cuda_fp16.h>
#include <math.h>
#include <stdint.h>

typedef unsigned long long u64;
typedef __half h16;

#define BB 2
#define SS 1024
#define HID 3072
#define NH 16
#define QL 1536
#define KVL 512
#define NOPEd 128
#define ROPEd 64
#define QKD 192
#define VHD 128
#define NT (BB*SS)
#define KVOUT 256
#define QKVN 2176
#define QKVW 2112
#define SCALE 0.07216878364870323f

// ------------------------------------------------------------------
// scratch (device globals)
// ------------------------------------------------------------------
#define AL __align__(256)
__device__ AL h16   g_hs  [NT*HID];
__device__ AL h16   g_wqkva[QKVN*HID];
__device__ AL float g_bqkva[QKVN];
__device__ AL h16   g_wqb [HID*QL];
__device__ AL h16   g_wkvb[NH*KVOUT*KVL];
__device__ AL h16   g_wo  [HID*NH*VHD];
__device__ AL float g_qkv [NT*QKVN];
__device__ AL h16   g_qln [NT*QL];
__device__ AL h16   g_kvln[NT*KVL];
__device__ AL h16   g_Qh  [(u64)BB*NH*SS*QKD];
__device__ AL h16   g_Kh  [(u64)BB*NH*SS*QKD];
__device__ AL h16   g_Vt  [(u64)BB*NH*VHD*SS];    /* [b][h][d][t] */
__device__ AL h16   g_at  [NT*NH*VHD];

// ------------------------------------------------------------------
// PTX helpers
// ------------------------------------------------------------------
__device__ __forceinline__ uint32_t smem_u32(const void* p) {
    uint32_t a;
    asm("{ .reg .u64 t; cvta.to.shared.u64 t, %1; cvt.u32.u64 %0, t; }" : "=r"(a) : "l"(p));
    return a;
}
__device__ __forceinline__ void cp16(uint32_t dst, const void* src) {
    asm volatile("cp.async.cg.shared.global [%0], [%1], 16;" :: "r"(dst), "l"(src));
}
__device__ __forceinline__ void cp_commit() {
    asm volatile("cp.async.commit_group;" ::: "memory");
}
template<int N> __device__ __forceinline__ void cp_wait() {
    asm volatile("cp.async.wait_group %0;" :: "n"(N) : "memory");
}
__device__ __forceinline__ void ldm4(uint32_t* r, uint32_t addr) {
    asm volatile("ldmatrix.sync.aligned.m8n8.x4.shared.b16 {%0,%1,%2,%3}, [%4];"
        : "=r"(r[0]), "=r"(r[1]), "=r"(r[2]), "=r"(r[3]) : "r"(addr));
}
__device__ __forceinline__ void mma_f16(float* c, const uint32_t* a, uint32_t b0, uint32_t b1) {
    asm volatile(
        "mma.sync.aligned.m16n8k16.row.col.f32.f16.f16.f32 "
        "{%0,%1,%2,%3}, {%4,%5,%6,%7}, {%8,%9}, {%0,%1,%2,%3};"
        : "+f"(c[0]), "+f"(c[1]), "+f"(c[2]), "+f"(c[3])
        : "r"(a[0]), "r"(a[1]), "r"(a[2]), "r"(a[3]), "r"(b0), "r"(b1));
}
__device__ __forceinline__ uint32_t pack2(float x, float y) {
    __half2 h = __floats2half2_rn(x, y);
    return *(uint32_t*)&h;
}

// ------------------------------------------------------------------
// fp16 GEMM: C = A @ B^T + bias, tile 128x128, BK=32, 4-stage pipeline
// mode 0: float out (stride ldc, store-guard n<Nw)
// mode 1: Q head-gather + RoPE -> g_Qh      (N = 3072)
// mode 2: KV head-gather -> g_Kh / g_Vt     (N = 4096)
// ------------------------------------------------------------------
#define LDSX 40
#define TSZ  (128*LDSX)
#define STGB (2*TSZ*2)
#define NSTG 4
#define SMEM_BYTES (NSTG*STGB)   /* 81920 */

__global__ void __launch_bounds__(256, 1)
k_mma(const h16* __restrict__ A, const h16* __restrict__ B,
      float* __restrict__ C, const float* __restrict__ bias,
      int M, int N, int K, int Nw, int ldc, int mode)
{
    extern __shared__ h16 sm[];
    const uint32_t sb = smem_u32(sm);
    const int tid  = threadIdx.x;
    const int wid  = tid >> 5, lane = tid & 31;
    const int wm   = (wid & 1) * 64;
    const int wn   = (wid >> 1) * 32;
    const int m0   = blockIdx.y * 128, n0 = blockIdx.x * 128;

    const u64 aoff0 = (u64)m0 * K;
    const u64 boff0 = (u64)n0 * K;
    const int NC = K >> 5;

    auto fill = [&](int stage, int c) {
        const uint32_t sbase = sb + stage * STGB;
        const u64 ka = aoff0 + c * 32;
        const u64 kb = boff0 + c * 32;
#pragma unroll
        for (int j = 0; j < 4; ++j) {
            const int i   = tid + j * 256;       // 0..1023
            const int t   = i >> 9;              // 0:A 1:B
            const int row = (i >> 2) & 127;
            const int ch  = i & 3;
            const h16* g  = (t == 0) ? A : B;
            const u64 base = (t == 0) ? ka : kb;
            const uint32_t dst = sbase + (t * TSZ + row * LDSX + ch * 8) * 2;
            cp16(dst, g + base + (u64)row * K + ch * 8);
        }
    };

    float acc[4][4][4];
#pragma unroll
    for (int a = 0; a < 4; ++a)
#pragma unroll
        for (int b = 0; b < 4; ++b)
#pragma unroll
            for (int d = 0; d < 4; ++d) acc[a][b][d] = 0.f;

#pragma unroll
    for (int p = 0; p < NSTG - 1; ++p) { if (p < NC) fill(p, p); cp_commit(); }

    const int a_row = lane & 15;
    const int a_kof = (lane >> 4) * 8;
    const int b_row = (lane & 7) + ((lane >> 4) & 1) * 8;
    const int b_kof = ((lane >> 3) & 1) * 8;

    for (int c = 0; c < NC; ++c) {
        cp_wait<NSTG - 2>();
        __syncthreads();
        if (c + NSTG - 1 < NC) fill((c + NSTG - 1) & (NSTG - 1), c + NSTG - 1);
        cp_commit();

        const uint32_t st = sb + (c & (NSTG - 1)) * STGB;
#pragma unroll
        for (int ks = 0; ks < 2; ++ks) {
            const int k0s = ks * 16;
            uint32_t aS[4][4], bS[2][4];
#pragma unroll
            for (int mi = 0; mi < 4; ++mi)
                ldm4(aS[mi], st + ((wm + mi * 16 + a_row) * LDSX + k0s + a_kof) * 2);
#pragma unroll
            for (int np = 0; np < 2; ++np)
                ldm4(bS[np], st + (TSZ + (wn + np * 16 + b_row) * LDSX + k0s + b_kof) * 2);
#pragma unroll
            for (int mi = 0; mi < 4; ++mi) {
#pragma unroll
                for (int ni = 0; ni < 4; ++ni) {
                    mma_f16(acc[mi][ni], aS[mi],
                            bS[ni >> 1][(ni & 1) * 2], bS[ni >> 1][(ni & 1) * 2 + 1]);
                }
            }
        }
    }

    const int er = lane >> 2;
    const int ec = (lane & 3) * 2;
#pragma unroll
    for (int mi = 0; mi < 4; ++mi) {
#pragma unroll
        for (int ni = 0; ni < 4; ++ni) {
            const int mrow = m0 + wm + mi * 16 + er;
            const int n = n0 + wn + ni * 8 + ec;
            const float* ac = acc[mi][ni];
            if (mode == 0) {
                if (n < Nw) {
                    const float b0 = bias[n], b1 = bias[n + 1];
                    *(float2*)&C[(u64)mrow * ldc + n]       = make_float2(ac[0] + b0, ac[1] + b1);
                    *(float2*)&C[(u64)(mrow + 8) * ldc + n] = make_float2(ac[2] + b0, ac[3] + b1);
                }
            } else if (mode == 1) {
                const int h = n / QKD, d = n - h * QKD;
#pragma unroll
                for (int r = 0; r < 2; ++r) {
                    const int m = mrow + r * 8;
                    const int b = m >> 10, s = m & (SS - 1);
                    float v0 = ac[2 * r]     + bias[n];
                    float v1 = ac[2 * r + 1] + bias[n + 1];
                    if (d >= NOPEd) {
                        const int i = (d - NOPEd) >> 1;
                        float inv = powf(10000.f, -(float)(2 * i) / (float)ROPEd);
                        float sn, cs; sincosf((float)s * inv, &sn, &cs);
                        float r1 = v0 * cs - v1 * sn;
                        float r2 = v0 * sn + v1 * cs;
                        v0 = r1; v1 = r2;
                    }
                    const u64 o = ((u64)(b * NH + h) * SS + s) * QKD + d;
                    g_Qh[o]     = __float2half_rn(v0);
                    g_Qh[o + 1] = __float2half_rn(v1);
                }
            } else {
                const int h = n >> 8, cc = n & 255;
#pragma unroll
                for (int r = 0; r < 2; ++r) {
                    const int m = mrow + r * 8;
                    const int b = m >> 10, s = m & (SS - 1);
                    const float v0 = ac[2 * r]     + bias[n];
                    const float v1 = ac[2 * r + 1] + bias[n + 1];
                    if (cc < NOPEd) {
                        const u64 o = ((u64)(b * NH + h) * SS + s) * QKD + cc;
                        g_Kh[o]     = __float2half_rn(v0);
                        g_Kh[o + 1] = __float2half_rn(v1);
                    } else {
                        const int d = cc - NOPEd;
                        const u64 o = ((u64)(b * NH + h) * VHD + d) * SS + s;
                        g_Vt[o]      = __float2half_rn(v0);
                        g_Vt[o + SS] = __float2half_rn(v1);
                    }
                }
            }
        }
    }
}

// ------------------------------------------------------------------
// fused flash attention (causal): per CTA 128 q-rows of one (b,h)
// smem: Q [128][200], K [128][200], V [128][136]
// ------------------------------------------------------------------
#define QSTR 200
#define VSTR 136
#define FA_QBYTES (128*QSTR*2)            /* 51200 */
#define FA_KOFF   FA_QBYTES
#define FA_VOFF   (2*FA_QBYTES)           /* 102400 */
#define FA_SMEM   (FA_VOFF + 128*VSTR*2)  /* 137216 */

__global__ void __launch_bounds__(256, 1)
k_fa()
{
    extern __shared__ h16 sm[];
    const uint32_t sb = smem_u32(sm);
    const int tid  = threadIdx.x;
    const int wid  = tid >> 5, lane = tid & 31;
    const int qt   = (int)(gridDim.x - 1 - blockIdx.x);   // heavy tiles first
    const int z    = blockIdx.y;
    const int m0   = qt * 128;

    const h16* gQ = g_Qh + (u64)z * SS * QKD;
    const h16* gK = g_Kh + (u64)z * SS * QKD;
    const h16* gV = g_Vt + (u64)z * VHD * SS;

    // prologue: Q + K chunk 0
#pragma unroll
    for (int j = 0; j < 12; ++j) {
        const int i = tid + j * 256;
        const int r = i / 24, c = i % 24;
        cp16(sb + (r * QSTR + c * 8) * 2,           gQ + ((u64)(m0 + r)) * QKD + c * 8);
        cp16(sb + FA_KOFF + (r * QSTR + c * 8) * 2, gK + (u64)r * QKD + c * 8);
    }
    cp_commit();

    const int a_row = lane & 15;
    const int a_kof = (lane >> 4) * 8;
    const int b_row = (lane & 7) + ((lane >> 4) & 1) * 8;
    const int b_kof = ((lane >> 3) & 1) * 8;
    const int er = lane >> 2;
    const int ec = (lane & 3) * 2;
    const int row0 = m0 + wid * 16 + er;
    const int row1 = row0 + 8;

    float o[16][4];
#pragma unroll
    for (int nb = 0; nb < 16; ++nb)
#pragma unroll
        for (int e = 0; e < 4; ++e) o[nb][e] = 0.f;
    float mr0 = -1e30f, mr1 = -1e30f, lr0 = 0.f, lr1 = 0.f;

    for (int j = 0; j <= qt; ++j) {
        // issue V_j
#pragma unroll
        for (int t = 0; t < 8; ++t) {
            const int i = tid + t * 256;
            const int r = i >> 4, c = i & 15;
            cp16(sb + FA_VOFF + (r * VSTR + c * 8) * 2,
                 gV + (u64)r * SS + j * 128 + c * 8);
        }
        cp_commit();
        cp_wait<1>();
        __syncthreads();

        float sc[16][4];
#pragma unroll
        for (int nb = 0; nb < 16; ++nb)
#pragma unroll
            for (int e = 0; e < 4; ++e) sc[nb][e] = 0.f;

#pragma unroll
        for (int ks = 0; ks < 12; ++ks) {
            const int k0 = ks * 16;
            uint32_t aS[4];
            ldm4(aS, sb + ((wid * 16 + a_row) * QSTR + k0 + a_kof) * 2);
#pragma unroll
            for (int g = 0; g < 8; ++g) {
                uint32_t bK[4];
                ldm4(bK, sb + FA_KOFF + ((g * 16 + b_row) * QSTR + k0 + b_kof) * 2);
                mma_f16(sc[2 * g],     aS, bK[0], bK[1]);
                mma_f16(sc[2 * g + 1], aS, bK[2], bK[3]);
            }
        }
        __syncthreads();

        if (j < qt) {
#pragma unroll
            for (int t = 0; t < 12; ++t) {
                const int i = tid + t * 256;
                const int r = i / 24, c = i % 24;
                cp16(sb + FA_KOFF + (r * QSTR + c * 8) * 2,
                     gK + ((u64)(j + 1) * 128 + r) * QKD + c * 8);
            }
            cp_commit();
        }

#pragma unroll
        for (int nb = 0; nb < 16; ++nb)
#pragma unroll
            for (int e = 0; e < 4; ++e) sc[nb][e] *= SCALE;
        if (j == qt) {
#pragma unroll
            for (int nb = 0; nb < 16; ++nb) {
                const int col = j * 128 + nb * 8 + ec;
                if (col     > row0) sc[nb][0] = -1e30f;
                if (col + 1 > row0) sc[nb][1] = -1e30f;
                if (col     > row1) sc[nb][2] = -1e30f;
                if (col + 1 > row1) sc[nb][3] = -1e30f;
            }
        }
        float mx0 = -1e30f, mx1 = -1e30f;
#pragma unroll
        for (int nb = 0; nb < 16; ++nb) {
            mx0 = fmaxf(mx0, fmaxf(sc[nb][0], sc[nb][1]));
            mx1 = fmaxf(mx1, fmaxf(sc[nb][2], sc[nb][3]));
        }
        mx0 = fmaxf(mx0, __shfl_xor_sync(0xFFFFFFFFu, mx0, 1));
        mx0 = fmaxf(mx0, __shfl_xor_sync(0xFFFFFFFFu, mx0, 2));
        mx1 = fmaxf(mx1, __shfl_xor_sync(0xFFFFFFFFu, mx1, 1));
        mx1 = fmaxf(mx1, __shfl_xor_sync(0xFFFFFFFFu, mx1, 2));
        const float mn0 = fmaxf(mr0, mx0), mn1 = fmaxf(mr1, mx1);
        const float al0 = __expf(mr0 - mn0), al1 = __expf(mr1 - mn1);
        mr0 = mn0; mr1 = mn1;
        float s0 = 0.f, s1 = 0.f;
#pragma unroll
        for (int nb = 0; nb < 16; ++nb) {
            sc[nb][0] = __expf(sc[nb][0] - mn0); s0 += sc[nb][0];
            sc[nb][1] = __expf(sc[nb][1] - mn0); s0 += sc[nb][1];
            sc[nb][2] = __expf(sc[nb][2] - mn1); s1 += sc[nb][2];
            sc[nb][3] = __expf(sc[nb][3] - mn1); s1 += sc[nb][3];
        }
        s0 += __shfl_xor_sync(0xFFFFFFFFu, s0, 1);
        s0 += __shfl_xor_sync(0xFFFFFFFFu, s0, 2);
        s1 += __shfl_xor_sync(0xFFFFFFFFu, s1, 1);
        s1 += __shfl_xor_sync(0xFFFFFFFFu, s1, 2);
        lr0 = lr0 * al0 + s0;
        lr1 = lr1 * al1 + s1;
#pragma unroll
        for (int nb = 0; nb < 16; ++nb) {
            o[nb][0] *= al0; o[nb][1] *= al0;
            o[nb][2] *= al1; o[nb][3] *= al1;
        }

        if (j < qt) cp_wait<1>(); else cp_wait<0>();
        __syncthreads();
#pragma unroll
        for (int t = 0; t < 8; ++t) {
            uint32_t aP[4];
            aP[0] = pack2(sc[2 * t][0],     sc[2 * t][1]);
            aP[1] = pack2(sc[2 * t][2],     sc[2 * t][3]);
            aP[2] = pack2(sc[2 * t + 1][0], sc[2 * t + 1][1]);
            aP[3] = pack2(sc[2 * t + 1][2], sc[2 * t + 1][3]);
#pragma unroll
            for (int g = 0; g < 8; ++g) {
                uint32_t bV[4];
                ldm4(bV, sb + FA_VOFF + ((g * 16 + b_row) * VSTR + t * 16 + b_kof) * 2);
                mma_f16(o[2 * g],     aP, bV[0], bV[1]);
                mma_f16(o[2 * g + 1], aP, bV[2], bV[3]);
            }
        }
        __syncthreads();
    }

    const float i0 = 1.0f / lr0, i1 = 1.0f / lr1;
    const int b = z >> 4, h = z & 15;
#pragma unroll
    for (int nb = 0; nb < 16; ++nb) {
        const int d = nb * 8 + ec;
        const u64 r0o = (u64)(b * SS + row0) * (NH * VHD) + (u64)h * VHD + d;
        const u64 r1o = (u64)(b * SS + row1) * (NH * VHD) + (u64)h * VHD + d;
        g_at[r0o]     = __float2half_rn(o[nb][0] * i0);
        g_at[r0o + 1] = __float2half_rn(o[nb][1] * i0);
        g_at[r1o]     = __float2half_rn(o[nb][2] * i1);
        g_at[r1o + 1] = __float2half_rn(o[nb][3] * i1);
    }
}

// ------------------------------------------------------------------
// elementwise kernels
// ------------------------------------------------------------------
__global__ void k_split1(const float* __restrict__ x, h16* __restrict__ o, int n)
{
    int i = blockIdx.x * 256 + threadIdx.x;
    if (i >= n) return;
    o[i] = __float2half_rn(x[i]);
}

__global__ void k_pack_wa(const float* __restrict__ wqa, const float* __restrict__ wkva)
{
    int c = blockIdx.x * 256 + threadIdx.x;
    int r = blockIdx.y;
    if (c >= HID) return;
    float v = 0.f;
    if (r < QL)        v = wqa[(u64)r * HID + c];
    else if (r < QKVW) v = wkva[(u64)(r - QL) * HID + c];
    g_wqkva[(u64)r * HID + c] = __float2half_rn(v);
}

__global__ void k_pack_bias(const float* __restrict__ bqa, const float* __restrict__ bkva)
{
    int i = blockIdx.x * 256 + threadIdx.x;
    if (i >= QKVN) return;
    float v = 0.f;
    if (i < QL)        v = bqa[i];
    else if (i < QKVW) v = bkva[i - QL];
    g_bqkva[i] = v;
}

__global__ void __launch_bounds__(256)
k_rmsnorm(const float* __restrict__ X, const float* __restrict__ w,
          h16* __restrict__ Y, int W, int inStride, int outStride)
{
    int row = blockIdx.x;
    const float* x = X + (u64)row * inStride;
    float s = 0.f;
    for (int i = threadIdx.x; i < W; i += 256) { float v = x[i]; s += v * v; }
    __shared__ float red[256];
    red[threadIdx.x] = s; __syncthreads();
    for (int off = 128; off > 0; off >>= 1) {
        if (threadIdx.x < off) red[threadIdx.x] += red[threadIdx.x + off];
        __syncthreads();
    }
    float r = rsqrtf(red[0] / (float)W + 1e-6f);
    h16* y = Y + (u64)row * outStride;
    for (int i = threadIdx.x; i < W; i += 256)
        y[i] = __float2half_rn(w[i] * (x[i] * r));
}

// K rope columns (128..191) for all heads, from g_qkv's k_rope slice
__global__ void k_prep_krope()
{
    int idx = blockIdx.x * 256 + threadIdx.x;
    if (idx >= BB * SS * (ROPEd / 2)) return;
    int i = idx & 31;
    int s = (idx >> 5) & (SS - 1);
    int b = idx >> 15;
    const float* kr = g_qkv + (u64)(b * SS + s) * QKVN + (QL + KVL);
    float x1 = kr[2 * i], x2 = kr[2 * i + 1];
    float inv = powf(10000.f, -(float)(2 * i) / (float)ROPEd);
    float sn, cs; sincosf((float)s * inv, &sn, &cs);
    h16 r1 = __float2half_rn(x1 * cs - x2 * sn);
    h16 r2 = __float2half_rn(x1 * sn + x2 * cs);
#pragma unroll
    for (int h = 0; h < NH; ++h) {
        u64 o = ((u64)(b * NH + h) * SS + s) * QKD + NOPEd + 2 * i;
        g_Kh[o] = r1; g_Kh[o + 1] = r2;
    }
}

// ------------------------------------------------------------------
// launch (two-stream fork/join, graph-capture-safe)
// ------------------------------------------------------------------
static inline void* sym(const void* s) { void* p; cudaGetSymbolAddress(&p, s); return p; }

extern "C" void kernel_launch(void* const* d_in, const int* in_sizes, int n_in,
                              void* d_out, int out_size)
{
    const float* hs        = (const float*)d_in[0];
    const float* wq_a_w    = (const float*)d_in[2];
    const float* wq_a_b    = (const float*)d_in[3];
    const float* q_norm_w  = (const float*)d_in[4];
    const float* wq_b_w    = (const float*)d_in[5];
    const float* wq_b_b    = (const float*)d_in[6];
    const float* wkv_a_w   = (const float*)d_in[7];
    const float* wkv_a_b   = (const float*)d_in[8];
    const float* kv_norm_w = (const float*)d_in[9];
    const float* wkv_b_w   = (const float*)d_in[10];
    const float* wkv_b_b   = (const float*)d_in[11];
    const float* wo_w      = (const float*)d_in[12];
    const float* wo_b      = (const float*)d_in[13];
    float* out = (float*)d_out;

    static bool init = false;
    static cudaStream_t s1;
    static cudaEvent_t e0, e_wqb, e_g13, e_kv;
    if (!init) {
        cudaFuncSetAttribute(k_mma, cudaFuncAttributeMaxDynamicSharedMemorySize, SMEM_BYTES);
        cudaFuncSetAttribute(k_fa,  cudaFuncAttributeMaxDynamicSharedMemorySize, FA_SMEM);
        cudaStreamCreateWithFlags(&s1, cudaStreamNonBlocking);
        cudaEventCreateWithFlags(&e0,    cudaEventDisableTiming);
        cudaEventCreateWithFlags(&e_wqb, cudaEventDisableTiming);
        cudaEventCreateWithFlags(&e_g13, cudaEventDisableTiming);
        cudaEventCreateWithFlags(&e_kv,  cudaEventDisableTiming);
        init = true;
    }

    h16 *hsp=(h16*)sym(g_hs);
    h16 *wqkva=(h16*)sym(g_wqkva);
    float *bqkva=(float*)sym(g_bqkva);
    h16 *wqb=(h16*)sym(g_wqb), *wkvb=(h16*)sym(g_wkvb), *wo=(h16*)sym(g_wo);
    float *qkv=(float*)sym(g_qkv);
    h16 *qln=(h16*)sym(g_qln), *kvln=(h16*)sym(g_kvln);
    h16 *at=(h16*)sym(g_at);

    // fork: side stream does the weight converts for later GEMMs
    cudaEventRecord(e0, 0);
    cudaStreamWaitEvent(s1, e0, 0);
    k_split1<<<(HID*QL + 255)/256, 256, 0, s1>>>(wq_b_w, wqb, HID*QL);
    cudaEventRecord(e_wqb, s1);
    k_split1<<<(NH*KVOUT*KVL + 255)/256, 256, 0, s1>>>(wkv_b_w, wkvb, NH*KVOUT*KVL);
    k_split1<<<(HID*NH*VHD + 255)/256, 256, 0, s1>>>(wo_w, wo, HID*NH*VHD);

    // main stream: inputs for merged first GEMM
    k_split1<<<(NT*HID + 255)/256, 256>>>(hs, hsp, NT*HID);
    k_pack_wa<<<dim3((HID + 255)/256, QKVN), 256>>>(wq_a_w, wkv_a_w);
    k_pack_bias<<<(QKVN + 255)/256, 256>>>(wq_a_b, wkv_a_b);

    // merged q_lat + kv_lat + k_rope projection
    k_mma<<<dim3(QKVN/128, NT/128), 256, SMEM_BYTES>>>(
        hsp, wqkva, qkv, bqkva, NT, QKVN, HID, QKVW, QKVN, 0);
    cudaEventRecord(e_g13, 0);

    // kv chain on side stream: krope + rmsnorm + fused wkv_b GEMM (writes Kh/Vt)
    cudaStreamWaitEvent(s1, e_g13, 0);
    k_prep_krope<<<(BB*SS*(ROPEd/2) + 255)/256, 256, 0, s1>>>();
    k_rmsnorm<<<NT, 256, 0, s1>>>(qkv + QL, kv_norm_w, kvln, KVL, QKVN, KVL);
    k_mma<<<dim3(NH*KVOUT/128, NT/128), 256, SMEM_BYTES, s1>>>(
        kvln, wkvb, nullptr, wkv_b_b, NT, NH*KVOUT, KVL, NH*KVOUT, NH*KVOUT, 2);
    cudaEventRecord(e_kv, s1);

    // q chain on main stream: rmsnorm + fused wq_b GEMM (writes Qh + rope)
    k_rmsnorm<<<NT, 256>>>(qkv, q_norm_w, qln, QL, QKVN, QL);
    cudaStreamWaitEvent(0, e_wqb, 0);
    k_mma<<<dim3(HID/128, NT/128), 256, SMEM_BYTES>>>(
        qln, wqb, nullptr, wq_b_b, NT, HID, QL, HID, HID, 1);

    // join kv chain, then fused flash attention
    cudaStreamWaitEvent(0, e_kv, 0);
    k_fa<<<dim3(SS/128, BB*NH), 256, FA_SMEM>>>();

    // output projection
    k_mma<<<dim3(HID/128, NT/128), 256, SMEM_BYTES>>>(
        at, wo, out, wo_b, NT, HID, NH*VHD, HID, HID, 0);
}

// round 15
// speedup vs baseline: 2.5404x; 1.1574x over previous
#include <cuda_runtime.h>
#include <cuda_fp16.h>
#include <math.h>
#include <stdint.h>

typedef unsigned long long u64;
typedef __half h16;

#define BB 2
#define SS 1024
#define HID 3072
#define NH 16
#define QL 1536
#define KVL 512
#define NOPEd 128
#define ROPEd 64
#define QKD 192
#define VHD 128
#define NT (BB*SS)
#define KVOUT 256
#define QKVN 2176
#define QKVW 2112
#define SCALE 0.07216878364870323f

// ------------------------------------------------------------------
// scratch (device globals)
// ------------------------------------------------------------------
#define AL __align__(256)
__device__ AL h16   g_hs  [NT*HID];
__device__ AL h16   g_wqkva[QKVN*HID];
__device__ AL float g_bqkva[QKVN];
__device__ AL h16   g_wqb [HID*QL];
__device__ AL h16   g_wkvb[NH*KVOUT*KVL];
__device__ AL h16   g_wo  [HID*NH*VHD];
__device__ AL float g_qkv [NT*QKVN];
__device__ AL h16   g_qln [NT*QL];
__device__ AL h16   g_kvln[NT*KVL];
__device__ AL h16   g_Qh  [(u64)BB*NH*SS*QKD];
__device__ AL h16   g_Kh  [(u64)BB*NH*SS*QKD];
__device__ AL h16   g_Vt  [(u64)BB*NH*VHD*SS];    /* [b][h][d][t] */
__device__ AL h16   g_at  [NT*NH*VHD];

// ------------------------------------------------------------------
// PTX helpers
// ------------------------------------------------------------------
__device__ __forceinline__ uint32_t smem_u32(const void* p) {
    uint32_t a;
    asm("{ .reg .u64 t; cvta.to.shared.u64 t, %1; cvt.u32.u64 %0, t; }" : "=r"(a) : "l"(p));
    return a;
}
__device__ __forceinline__ void cp16(uint32_t dst, const void* src) {
    asm volatile("cp.async.cg.shared.global [%0], [%1], 16;" :: "r"(dst), "l"(src));
}
__device__ __forceinline__ void cp_commit() {
    asm volatile("cp.async.commit_group;" ::: "memory");
}
template<int N> __device__ __forceinline__ void cp_wait() {
    asm volatile("cp.async.wait_group %0;" :: "n"(N) : "memory");
}
__device__ __forceinline__ void ldm4(uint32_t* r, uint32_t addr) {
    asm volatile("ldmatrix.sync.aligned.m8n8.x4.shared.b16 {%0,%1,%2,%3}, [%4];"
        : "=r"(r[0]), "=r"(r[1]), "=r"(r[2]), "=r"(r[3]) : "r"(addr));
}
__device__ __forceinline__ void mma_f16(float* c, const uint32_t* a, uint32_t b0, uint32_t b1) {
    asm volatile(
        "mma.sync.aligned.m16n8k16.row.col.f32.f16.f16.f32 "
        "{%0,%1,%2,%3}, {%4,%5,%6,%7}, {%8,%9}, {%0,%1,%2,%3};"
        : "+f"(c[0]), "+f"(c[1]), "+f"(c[2]), "+f"(c[3])
        : "r"(a[0]), "r"(a[1]), "r"(a[2]), "r"(a[3]), "r"(b0), "r"(b1));
}
__device__ __forceinline__ uint32_t pack2(float x, float y) {
    __half2 h = __floats2half2_rn(x, y);
    return *(uint32_t*)&h;
}

// ------------------------------------------------------------------
// fp16 GEMM: C = A @ B^T + bias, tile 128x128, BK=32, 4-stage pipeline
// 2 CTAs/SM co-residency (164KB smem, <=128 regs)
// mode 0: float out (stride ldc, store-guard n<Nw)
// mode 1: Q head-gather + RoPE -> g_Qh      (N = 3072)
// mode 2: KV head-gather -> g_Kh / g_Vt     (N = 4096)
// ------------------------------------------------------------------
#define LDSX 40
#define TSZ  (128*LDSX)
#define STGB (2*TSZ*2)
#define NSTG 4
#define SMEM_BYTES (NSTG*STGB)   /* 81920 */

__global__ void __launch_bounds__(256, 2)
k_mma(const h16* __restrict__ A, const h16* __restrict__ B,
      float* __restrict__ C, const float* __restrict__ bias,
      int M, int N, int K, int Nw, int ldc, int mode)
{
    extern __shared__ h16 sm[];
    const uint32_t sb = smem_u32(sm);
    const int tid  = threadIdx.x;
    const int wid  = tid >> 5, lane = tid & 31;
    const int wm   = (wid & 1) * 64;
    const int wn   = (wid >> 1) * 32;
    const int m0   = blockIdx.y * 128, n0 = blockIdx.x * 128;

    const u64 aoff0 = (u64)m0 * K;
    const u64 boff0 = (u64)n0 * K;
    const int NC = K >> 5;

    auto fill = [&](int stage, int c) {
        const uint32_t sbase = sb + stage * STGB;
        const u64 ka = aoff0 + c * 32;
        const u64 kb = boff0 + c * 32;
#pragma unroll
        for (int j = 0; j < 4; ++j) {
            const int i   = tid + j * 256;       // 0..1023
            const int t   = i >> 9;              // 0:A 1:B
            const int row = (i >> 2) & 127;
            const int ch  = i & 3;
            const h16* g  = (t == 0) ? A : B;
            const u64 base = (t == 0) ? ka : kb;
            const uint32_t dst = sbase + (t * TSZ + row * LDSX + ch * 8) * 2;
            cp16(dst, g + base + (u64)row * K + ch * 8);
        }
    };

    float acc[4][4][4];
#pragma unroll
    for (int a = 0; a < 4; ++a)
#pragma unroll
        for (int b = 0; b < 4; ++b)
#pragma unroll
            for (int d = 0; d < 4; ++d) acc[a][b][d] = 0.f;

#pragma unroll
    for (int p = 0; p < NSTG - 1; ++p) { if (p < NC) fill(p, p); cp_commit(); }

    const int a_row = lane & 15;
    const int a_kof = (lane >> 4) * 8;
    const int b_row = (lane & 7) + ((lane >> 4) & 1) * 8;
    const int b_kof = ((lane >> 3) & 1) * 8;

    for (int c = 0; c < NC; ++c) {
        cp_wait<NSTG - 2>();
        __syncthreads();
        if (c + NSTG - 1 < NC) fill((c + NSTG - 1) & (NSTG - 1), c + NSTG - 1);
        cp_commit();

        const uint32_t st = sb + (c & (NSTG - 1)) * STGB;
#pragma unroll
        for (int ks = 0; ks < 2; ++ks) {
            const int k0s = ks * 16;
            uint32_t aS[4][4], bS[2][4];
#pragma unroll
            for (int mi = 0; mi < 4; ++mi)
                ldm4(aS[mi], st + ((wm + mi * 16 + a_row) * LDSX + k0s + a_kof) * 2);
#pragma unroll
            for (int np = 0; np < 2; ++np)
                ldm4(bS[np], st + (TSZ + (wn + np * 16 + b_row) * LDSX + k0s + b_kof) * 2);
#pragma unroll
            for (int mi = 0; mi < 4; ++mi) {
#pragma unroll
                for (int ni = 0; ni < 4; ++ni) {
                    mma_f16(acc[mi][ni], aS[mi],
                            bS[ni >> 1][(ni & 1) * 2], bS[ni >> 1][(ni & 1) * 2 + 1]);
                }
            }
        }
    }

    const int er = lane >> 2;
    const int ec = (lane & 3) * 2;
#pragma unroll
    for (int mi = 0; mi < 4; ++mi) {
#pragma unroll
        for (int ni = 0; ni < 4; ++ni) {
            const int mrow = m0 + wm + mi * 16 + er;
            const int n = n0 + wn + ni * 8 + ec;
            const float* ac = acc[mi][ni];
            if (mode == 0) {
                if (n < Nw) {
                    const float b0 = bias[n], b1 = bias[n + 1];
                    *(float2*)&C[(u64)mrow * ldc + n]       = make_float2(ac[0] + b0, ac[1] + b1);
                    *(float2*)&C[(u64)(mrow + 8) * ldc + n] = make_float2(ac[2] + b0, ac[3] + b1);
                }
            } else if (mode == 1) {
                const int h = n / QKD, d = n - h * QKD;
#pragma unroll
                for (int r = 0; r < 2; ++r) {
                    const int m = mrow + r * 8;
                    const int b = m >> 10, s = m & (SS - 1);
                    float v0 = ac[2 * r]     + bias[n];
                    float v1 = ac[2 * r + 1] + bias[n + 1];
                    if (d >= NOPEd) {
                        const int i = (d - NOPEd) >> 1;
                        float inv = powf(10000.f, -(float)(2 * i) / (float)ROPEd);
                        float sn, cs; sincosf((float)s * inv, &sn, &cs);
                        float r1 = v0 * cs - v1 * sn;
                        float r2 = v0 * sn + v1 * cs;
                        v0 = r1; v1 = r2;
                    }
                    const u64 o = ((u64)(b * NH + h) * SS + s) * QKD + d;
                    g_Qh[o]     = __float2half_rn(v0);
                    g_Qh[o + 1] = __float2half_rn(v1);
                }
            } else {
                const int h = n >> 8, cc = n & 255;
#pragma unroll
                for (int r = 0; r < 2; ++r) {
                    const int m = mrow + r * 8;
                    const int b = m >> 10, s = m & (SS - 1);
                    const float v0 = ac[2 * r]     + bias[n];
                    const float v1 = ac[2 * r + 1] + bias[n + 1];
                    if (cc < NOPEd) {
                        const u64 o = ((u64)(b * NH + h) * SS + s) * QKD + cc;
                        g_Kh[o]     = __float2half_rn(v0);
                        g_Kh[o + 1] = __float2half_rn(v1);
                    } else {
                        const int d = cc - NOPEd;
                        const u64 o = ((u64)(b * NH + h) * VHD + d) * SS + s;
                        g_Vt[o]      = __float2half_rn(v0);
                        g_Vt[o + SS] = __float2half_rn(v1);
                    }
                }
            }
        }
    }
}

// ------------------------------------------------------------------
// fused flash attention (causal): per CTA 128 q-rows of one (b,h)
// smem: Q [128][200], K [128][200], V [128][136]
// ------------------------------------------------------------------
#define QSTR 200
#define VSTR 136
#define FA_QBYTES (128*QSTR*2)            /* 51200 */
#define FA_KOFF   FA_QBYTES
#define FA_VOFF   (2*FA_QBYTES)           /* 102400 */
#define FA_SMEM   (FA_VOFF + 128*VSTR*2)  /* 137216 */

__global__ void __launch_bounds__(256, 1)
k_fa()
{
    extern __shared__ h16 sm[];
    const uint32_t sb = smem_u32(sm);
    const int tid  = threadIdx.x;
    const int wid  = tid >> 5, lane = tid & 31;
    const int qt   = (int)(gridDim.x - 1 - blockIdx.x);   // heavy tiles first
    const int z    = blockIdx.y;
    const int m0   = qt * 128;

    const h16* gQ = g_Qh + (u64)z * SS * QKD;
    const h16* gK = g_Kh + (u64)z * SS * QKD;
    const h16* gV = g_Vt + (u64)z * VHD * SS;

    // prologue: Q + K chunk 0
#pragma unroll
    for (int j = 0; j < 12; ++j) {
        const int i = tid + j * 256;
        const int r = i / 24, c = i % 24;
        cp16(sb + (r * QSTR + c * 8) * 2,           gQ + ((u64)(m0 + r)) * QKD + c * 8);
        cp16(sb + FA_KOFF + (r * QSTR + c * 8) * 2, gK + (u64)r * QKD + c * 8);
    }
    cp_commit();

    const int a_row = lane & 15;
    const int a_kof = (lane >> 4) * 8;
    const int b_row = (lane & 7) + ((lane >> 4) & 1) * 8;
    const int b_kof = ((lane >> 3) & 1) * 8;
    const int er = lane >> 2;
    const int ec = (lane & 3) * 2;
    const int row0 = m0 + wid * 16 + er;
    const int row1 = row0 + 8;

    float o[16][4];
#pragma unroll
    for (int nb = 0; nb < 16; ++nb)
#pragma unroll
        for (int e = 0; e < 4; ++e) o[nb][e] = 0.f;
    float mr0 = -1e30f, mr1 = -1e30f, lr0 = 0.f, lr1 = 0.f;

    for (int j = 0; j <= qt; ++j) {
        // issue V_j
#pragma unroll
        for (int t = 0; t < 8; ++t) {
            const int i = tid + t * 256;
            const int r = i >> 4, c = i & 15;
            cp16(sb + FA_VOFF + (r * VSTR + c * 8) * 2,
                 gV + (u64)r * SS + j * 128 + c * 8);
        }
        cp_commit();
        cp_wait<1>();
        __syncthreads();

        float sc[16][4];
#pragma unroll
        for (int nb = 0; nb < 16; ++nb)
#pragma unroll
            for (int e = 0; e < 4; ++e) sc[nb][e] = 0.f;

#pragma unroll
        for (int ks = 0; ks < 12; ++ks) {
            const int k0 = ks * 16;
            uint32_t aS[4];
            ldm4(aS, sb + ((wid * 16 + a_row) * QSTR + k0 + a_kof) * 2);
#pragma unroll
            for (int g = 0; g < 8; ++g) {
                uint32_t bK[4];
                ldm4(bK, sb + FA_KOFF + ((g * 16 + b_row) * QSTR + k0 + b_kof) * 2);
                mma_f16(sc[2 * g],     aS, bK[0], bK[1]);
                mma_f16(sc[2 * g + 1], aS, bK[2], bK[3]);
            }
        }
        __syncthreads();

        if (j < qt) {
#pragma unroll
            for (int t = 0; t < 12; ++t) {
                const int i = tid + t * 256;
                const int r = i / 24, c = i % 24;
                cp16(sb + FA_KOFF + (r * QSTR + c * 8) * 2,
                     gK + ((u64)(j + 1) * 128 + r) * QKD + c * 8);
            }
            cp_commit();
        }

#pragma unroll
        for (int nb = 0; nb < 16; ++nb)
#pragma unroll
            for (int e = 0; e < 4; ++e) sc[nb][e] *= SCALE;
        if (j == qt) {
#pragma unroll
            for (int nb = 0; nb < 16; ++nb) {
                const int col = j * 128 + nb * 8 + ec;
                if (col     > row0) sc[nb][0] = -1e30f;
                if (col + 1 > row0) sc[nb][1] = -1e30f;
                if (col     > row1) sc[nb][2] = -1e30f;
                if (col + 1 > row1) sc[nb][3] = -1e30f;
            }
        }
        float mx0 = -1e30f, mx1 = -1e30f;
#pragma unroll
        for (int nb = 0; nb < 16; ++nb) {
            mx0 = fmaxf(mx0, fmaxf(sc[nb][0], sc[nb][1]));
            mx1 = fmaxf(mx1, fmaxf(sc[nb][2], sc[nb][3]));
        }
        mx0 = fmaxf(mx0, __shfl_xor_sync(0xFFFFFFFFu, mx0, 1));
        mx0 = fmaxf(mx0, __shfl_xor_sync(0xFFFFFFFFu, mx0, 2));
        mx1 = fmaxf(mx1, __shfl_xor_sync(0xFFFFFFFFu, mx1, 1));
        mx1 = fmaxf(mx1, __shfl_xor_sync(0xFFFFFFFFu, mx1, 2));
        const float mn0 = fmaxf(mr0, mx0), mn1 = fmaxf(mr1, mx1);
        const float al0 = __expf(mr0 - mn0), al1 = __expf(mr1 - mn1);
        mr0 = mn0; mr1 = mn1;
        float s0 = 0.f, s1 = 0.f;
#pragma unroll
        for (int nb = 0; nb < 16; ++nb) {
            sc[nb][0] = __expf(sc[nb][0] - mn0); s0 += sc[nb][0];
            sc[nb][1] = __expf(sc[nb][1] - mn0); s0 += sc[nb][1];
            sc[nb][2] = __expf(sc[nb][2] - mn1); s1 += sc[nb][2];
            sc[nb][3] = __expf(sc[nb][3] - mn1); s1 += sc[nb][3];
        }
        s0 += __shfl_xor_sync(0xFFFFFFFFu, s0, 1);
        s0 += __shfl_xor_sync(0xFFFFFFFFu, s0, 2);
        s1 += __shfl_xor_sync(0xFFFFFFFFu, s1, 1);
        s1 += __shfl_xor_sync(0xFFFFFFFFu, s1, 2);
        lr0 = lr0 * al0 + s0;
        lr1 = lr1 * al1 + s1;
#pragma unroll
        for (int nb = 0; nb < 16; ++nb) {
            o[nb][0] *= al0; o[nb][1] *= al0;
            o[nb][2] *= al1; o[nb][3] *= al1;
        }

        if (j < qt) cp_wait<1>(); else cp_wait<0>();
        __syncthreads();
#pragma unroll
        for (int t = 0; t < 8; ++t) {
            uint32_t aP[4];
            aP[0] = pack2(sc[2 * t][0],     sc[2 * t][1]);
            aP[1] = pack2(sc[2 * t][2],     sc[2 * t][3]);
            aP[2] = pack2(sc[2 * t + 1][0], sc[2 * t + 1][1]);
            aP[3] = pack2(sc[2 * t + 1][2], sc[2 * t + 1][3]);
#pragma unroll
            for (int g = 0; g < 8; ++g) {
                uint32_t bV[4];
                ldm4(bV, sb + FA_VOFF + ((g * 16 + b_row) * VSTR + t * 16 + b_kof) * 2);
                mma_f16(o[2 * g],     aP, bV[0], bV[1]);
                mma_f16(o[2 * g + 1], aP, bV[2], bV[3]);
            }
        }
        __syncthreads();
    }

    const float i0 = 1.0f / lr0, i1 = 1.0f / lr1;
    const int b = z >> 4, h = z & 15;
#pragma unroll
    for (int nb = 0; nb < 16; ++nb) {
        const int d = nb * 8 + ec;
        const u64 r0o = (u64)(b * SS + row0) * (NH * VHD) + (u64)h * VHD + d;
        const u64 r1o = (u64)(b * SS + row1) * (NH * VHD) + (u64)h * VHD + d;
        g_at[r0o]     = __float2half_rn(o[nb][0] * i0);
        g_at[r0o + 1] = __float2half_rn(o[nb][1] * i0);
        g_at[r1o]     = __float2half_rn(o[nb][2] * i1);
        g_at[r1o + 1] = __float2half_rn(o[nb][3] * i1);
    }
}

// ------------------------------------------------------------------
// elementwise kernels
// ------------------------------------------------------------------
__global__ void k_split1(const float* __restrict__ x, h16* __restrict__ o, int n)
{
    int i = blockIdx.x * 256 + threadIdx.x;
    if (i >= n) return;
    o[i] = __float2half_rn(x[i]);
}

__global__ void k_pack_wa(const float* __restrict__ wqa, const float* __restrict__ wkva)
{
    int c = blockIdx.x * 256 + threadIdx.x;
    int r = blockIdx.y;
    if (c >= HID) return;
    float v = 0.f;
    if (r < QL)        v = wqa[(u64)r * HID + c];
    else if (r < QKVW) v = wkva[(u64)(r - QL) * HID + c];
    g_wqkva[(u64)r * HID + c] = __float2half_rn(v);
}

__global__ void k_pack_bias(const float* __restrict__ bqa, const float* __restrict__ bkva)
{
    int i = blockIdx.x * 256 + threadIdx.x;
    if (i >= QKVN) return;
    float v = 0.f;
    if (i < QL)        v = bqa[i];
    else if (i < QKVW) v = bkva[i - QL];
    g_bqkva[i] = v;
}

__global__ void __launch_bounds__(256)
k_rmsnorm(const float* __restrict__ X, const float* __restrict__ w,
          h16* __restrict__ Y, int W, int inStride, int outStride)
{
    int row = blockIdx.x;
    const float* x = X + (u64)row * inStride;
    float s = 0.f;
    for (int i = threadIdx.x; i < W; i += 256) { float v = x[i]; s += v * v; }
    __shared__ float red[256];
    red[threadIdx.x] = s; __syncthreads();
    for (int off = 128; off > 0; off >>= 1) {
        if (threadIdx.x < off) red[threadIdx.x] += red[threadIdx.x + off];
        __syncthreads();
    }
    float r = rsqrtf(red[0] / (float)W + 1e-6f);
    h16* y = Y + (u64)row * outStride;
    for (int i = threadIdx.x; i < W; i += 256)
        y[i] = __float2half_rn(w[i] * (x[i] * r));
}

// K rope columns (128..191) for all heads, from g_qkv's k_rope slice
__global__ void k_prep_krope()
{
    int idx = blockIdx.x * 256 + threadIdx.x;
    if (idx >= BB * SS * (ROPEd / 2)) return;
    int i = idx & 31;
    int s = (idx >> 5) & (SS - 1);
    int b = idx >> 15;
    const float* kr = g_qkv + (u64)(b * SS + s) * QKVN + (QL + KVL);
    float x1 = kr[2 * i], x2 = kr[2 * i + 1];
    float inv = powf(10000.f, -(float)(2 * i) / (float)ROPEd);
    float sn, cs; sincosf((float)s * inv, &sn, &cs);
    h16 r1 = __float2half_rn(x1 * cs - x2 * sn);
    h16 r2 = __float2half_rn(x1 * sn + x2 * cs);
#pragma unroll
    for (int h = 0; h < NH; ++h) {
        u64 o = ((u64)(b * NH + h) * SS + s) * QKD + NOPEd + 2 * i;
        g_Kh[o] = r1; g_Kh[o + 1] = r2;
    }
}

// ------------------------------------------------------------------
// launch (two-stream fork/join, graph-capture-safe)
// ------------------------------------------------------------------
static inline void* sym(const void* s) { void* p; cudaGetSymbolAddress(&p, s); return p; }

extern "C" void kernel_launch(void* const* d_in, const int* in_sizes, int n_in,
                              void* d_out, int out_size)
{
    const float* hs        = (const float*)d_in[0];
    const float* wq_a_w    = (const float*)d_in[2];
    const float* wq_a_b    = (const float*)d_in[3];
    const float* q_norm_w  = (const float*)d_in[4];
    const float* wq_b_w    = (const float*)d_in[5];
    const float* wq_b_b    = (const float*)d_in[6];
    const float* wkv_a_w   = (const float*)d_in[7];
    const float* wkv_a_b   = (const float*)d_in[8];
    const float* kv_norm_w = (const float*)d_in[9];
    const float* wkv_b_w   = (const float*)d_in[10];
    const float* wkv_b_b   = (const float*)d_in[11];
    const float* wo_w      = (const float*)d_in[12];
    const float* wo_b      = (const float*)d_in[13];
    float* out = (float*)d_out;

    static bool init = false;
    static cudaStream_t s1;
    static cudaEvent_t e0, e_wqb, e_g13, e_kv;
    if (!init) {
        cudaFuncSetAttribute(k_mma, cudaFuncAttributeMaxDynamicSharedMemorySize, SMEM_BYTES);
        cudaFuncSetAttribute(k_fa,  cudaFuncAttributeMaxDynamicSharedMemorySize, FA_SMEM);
        cudaStreamCreateWithFlags(&s1, cudaStreamNonBlocking);
        cudaEventCreateWithFlags(&e0,    cudaEventDisableTiming);
        cudaEventCreateWithFlags(&e_wqb, cudaEventDisableTiming);
        cudaEventCreateWithFlags(&e_g13, cudaEventDisableTiming);
        cudaEventCreateWithFlags(&e_kv,  cudaEventDisableTiming);
        init = true;
    }

    h16 *hsp=(h16*)sym(g_hs);
    h16 *wqkva=(h16*)sym(g_wqkva);
    float *bqkva=(float*)sym(g_bqkva);
    h16 *wqb=(h16*)sym(g_wqb), *wkvb=(h16*)sym(g_wkvb), *wo=(h16*)sym(g_wo);
    float *qkv=(float*)sym(g_qkv);
    h16 *qln=(h16*)sym(g_qln), *kvln=(h16*)sym(g_kvln);
    h16 *at=(h16*)sym(g_at);

    // fork: side stream does the weight converts for later GEMMs
    cudaEventRecord(e0, 0);
    cudaStreamWaitEvent(s1, e0, 0);
    k_split1<<<(HID*QL + 255)/256, 256, 0, s1>>>(wq_b_w, wqb, HID*QL);
    cudaEventRecord(e_wqb, s1);
    k_split1<<<(NH*KVOUT*KVL + 255)/256, 256, 0, s1>>>(wkv_b_w, wkvb, NH*KVOUT*KVL);
    k_split1<<<(HID*NH*VHD + 255)/256, 256, 0, s1>>>(wo_w, wo, HID*NH*VHD);

    // main stream: inputs for merged first GEMM
    k_split1<<<(NT*HID + 255)/256, 256>>>(hs, hsp, NT*HID);
    k_pack_wa<<<dim3((HID + 255)/256, QKVN), 256>>>(wq_a_w, wkv_a_w);
    k_pack_bias<<<(QKVN + 255)/256, 256>>>(wq_a_b, wkv_a_b);

    // merged q_lat + kv_lat + k_rope projection
    k_mma<<<dim3(QKVN/128, NT/128), 256, SMEM_BYTES>>>(
        hsp, wqkva, qkv, bqkva, NT, QKVN, HID, QKVW, QKVN, 0);
    cudaEventRecord(e_g13, 0);

    // kv chain on side stream: krope + rmsnorm + fused wkv_b GEMM (writes Kh/Vt)
    cudaStreamWaitEvent(s1, e_g13, 0);
    k_prep_krope<<<(BB*SS*(ROPEd/2) + 255)/256, 256, 0, s1>>>();
    k_rmsnorm<<<NT, 256, 0, s1>>>(qkv + QL, kv_norm_w, kvln, KVL, QKVN, KVL);
    k_mma<<<dim3(NH*KVOUT/128, NT/128), 256, SMEM_BYTES, s1>>>(
        kvln, wkvb, nullptr, wkv_b_b, NT, NH*KVOUT, KVL, NH*KVOUT, NH*KVOUT, 2);
    cudaEventRecord(e_kv, s1);

    // q chain on main stream: rmsnorm + fused wq_b GEMM (writes Qh + rope)
    k_rmsnorm<<<NT, 256>>>(qkv, q_norm_w, qln, QL, QKVN, QL);
    cudaStreamWaitEvent(0, e_wqb, 0);
    k_mma<<<dim3(HID/128, NT/128), 256, SMEM_BYTES>>>(
        qln, wqb, nullptr, wq_b_b, NT, HID, QL, HID, HID, 1);

    // join kv chain, then fused flash attention
    cudaStreamWaitEvent(0, e_kv, 0);
    k_fa<<<dim3(SS/128, BB*NH), 256, FA_SMEM>>>();

    // output projection
    k_mma<<<dim3(HID/128, NT/128), 256, SMEM_BYTES>>>(
        at, wo, out, wo_b, NT, HID, NH*VHD, HID, HID, 0);
}